// round 2
// baseline (speedup 1.0000x reference)
#include <cuda_runtime.h>

// EGNN layer, fused per-node kernel, round 2.
// B=2, N=16384, K=16, H=128.
// Block = 4 nodes, 64 threads (2 warps). Thread t: half=t/32 owns node pair
// {2*half, 2*half+1}; lane=t%32 owns output columns lane+32c, c=0..3.
// Shared-memory inputs are warp-broadcast; each LDS.128 now feeds 8 FFMA2
// (was 2), moving the bottleneck from the smem pipe to the fp32 FMA pipe.

#define HH   128
#define NB_  2
#define NN   16384
#define KK   16
#define NPB  4
#define PADK 20
#define NTH  64

typedef unsigned long long ull;

__device__ __forceinline__ ull pk2(float w) {
    ull r; asm("mov.b64 %0, {%1, %1};" : "=l"(r) : "f"(w)); return r;
}
__device__ __forceinline__ void fma2(ull &d, ull a, ull b) {
    asm("fma.rn.f32x2 %0, %1, %2, %0;" : "+l"(d) : "l"(a), "l"(b));
}
__device__ __forceinline__ float2 up2(ull v) {
    float2 f; asm("mov.b64 {%0, %1}, %2;" : "=f"(f.x), "=f"(f.y) : "l"(v)); return f;
}
__device__ __forceinline__ float silu_f(float v) { return v / (1.0f + __expf(-v)); }

// Shared-memory float offsets
#define OFF_HJT 0            // NPB*128*PADK = 10240 floats (holds m_ijT in phase 3)
#define OFF_M1T 10240        // 10240 floats (also prS [64][129] in coord reduce)
#define OFF_HIS 20480        // 512 floats, layout [channel][nb]
#define OFF_MIS 20992        // 512 floats, layout [channel][nb]
#define OFF_N1S 21504        // 512 floats, layout [channel][nb]
#define OFF_SQD 22016        // 64
#define OFF_XD  22080        // 192  [nb][k][d]
#define OFF_XI  22272        // 16 (12 used)
#define OFF_CW  22288        // 64
#define OFF_IDX 22352        // 64 ints
#define SMEM_FLOATS 22416
#define SMEM_BYTES (SMEM_FLOATS * 4)

// bp0/bp1: smem [128][PADK] bases for the thread's two nodes.
// Wb = W + lane; columns at +32c, rows stride HH.
// acc[nbl][kp][c] packs k-pair (2kp, 2kp+1).
__device__ __forceinline__ void gemm4(const float* __restrict__ bp0,
                                      const float* __restrict__ bp1,
                                      const float* __restrict__ Wb,
                                      ull (&acc)[2][8][4]) {
    float wbuf[4][4];
#pragma unroll
    for (int q = 0; q < 4; ++q)
#pragma unroll
        for (int c = 0; c < 4; ++c) wbuf[q][c] = Wb[q * HH + 32 * c];

#pragma unroll 1
    for (int ib = 0; ib < HH; ib += 4) {
        float wn[4][4];
#pragma unroll
        for (int q = 0; q < 4; ++q)
#pragma unroll
            for (int c = 0; c < 4; ++c) wn[q][c] = 0.0f;
        if (ib + 4 < HH) {
#pragma unroll
            for (int q = 0; q < 4; ++q)
#pragma unroll
                for (int c = 0; c < 4; ++c) wn[q][c] = Wb[(ib + 4 + q) * HH + 32 * c];
        }
#pragma unroll
        for (int q = 0; q < 4; ++q) {
            ull wp[4];
#pragma unroll
            for (int c = 0; c < 4; ++c) wp[c] = pk2(wbuf[q][c]);
#pragma unroll
            for (int nbl = 0; nbl < 2; ++nbl) {
                const float* bp = (nbl ? bp1 : bp0) + (ib + q) * PADK;
                ulonglong2 v0 = *(const ulonglong2*)(bp);
                ulonglong2 v1 = *(const ulonglong2*)(bp + 4);
                ulonglong2 v2 = *(const ulonglong2*)(bp + 8);
                ulonglong2 v3 = *(const ulonglong2*)(bp + 12);
#pragma unroll
                for (int c = 0; c < 4; ++c) {
                    fma2(acc[nbl][0][c], v0.x, wp[c]);
                    fma2(acc[nbl][1][c], v0.y, wp[c]);
                    fma2(acc[nbl][2][c], v1.x, wp[c]);
                    fma2(acc[nbl][3][c], v1.y, wp[c]);
                    fma2(acc[nbl][4][c], v2.x, wp[c]);
                    fma2(acc[nbl][5][c], v2.y, wp[c]);
                    fma2(acc[nbl][6][c], v3.x, wp[c]);
                    fma2(acc[nbl][7][c], v3.y, wp[c]);
                }
            }
        }
#pragma unroll
        for (int q = 0; q < 4; ++q)
#pragma unroll
            for (int c = 0; c < 4; ++c) wbuf[q][c] = wn[q][c];
    }
}

__global__ void __launch_bounds__(NTH, 2)
egnn_kernel(const float* __restrict__ h, const float* __restrict__ x,
            const int* __restrict__ eidx,
            const float* __restrict__ We1, const float* __restrict__ be1,
            const float* __restrict__ We2, const float* __restrict__ be2,
            const float* __restrict__ Wc1, const float* __restrict__ bc1,
            const float* __restrict__ Wc2,
            const float* __restrict__ Wn1, const float* __restrict__ bn1,
            const float* __restrict__ Wn2, const float* __restrict__ bn2,
            float* __restrict__ out) {
    extern __shared__ float sm[];
    float* hjT  = sm + OFF_HJT;
    float* m1T  = sm + OFF_M1T;
    float* prS  = sm + OFF_M1T;   // reuse: [64][129]
    float* hiS  = sm + OFF_HIS;
    float* miS  = sm + OFF_MIS;
    float* n1S  = sm + OFF_N1S;
    float* sqdS = sm + OFF_SQD;
    float* xdS  = sm + OFF_XD;
    float* xiS  = sm + OFF_XI;
    float* cwS  = sm + OFF_CW;
    int*   idxS = (int*)(sm + OFF_IDX);

    const int t    = threadIdx.x;
    const int half = t >> 5;
    const int lane = t & 31;
    const int g    = blockIdx.x;
    const int b    = g >> 12;                 // 4096 groups per batch
    const int n0   = (g & 4095) * NPB;
    const long base_bn = (long)b * NN;

    // ---- stage inputs ----
    idxS[t] = eidx[(base_bn + n0 + (t >> 4)) * KK + (t & 15)];
    if (t < NPB * 3) xiS[t] = x[(base_bn + n0 + t / 3) * 3 + (t % 3)];
#pragma unroll
    for (int r = 0; r < 2; ++r) {
        int ch = t + 64 * r;
        float4 hv;
        hv.x = h[(base_bn + n0 + 0) * HH + ch];
        hv.y = h[(base_bn + n0 + 1) * HH + ch];
        hv.z = h[(base_bn + n0 + 2) * HH + ch];
        hv.w = h[(base_bn + n0 + 3) * HH + ch];
        *(float4*)(hiS + ch * 4) = hv;
    }
    __syncthreads();

    // x_diff / sq_dist per edge (64 edges, 64 threads)
    {
        int j  = idxS[t];
        int nb = t >> 4;
        const float* xj = x + (base_bn + j) * 3;
        float dx = xiS[nb * 3 + 0] - xj[0];
        float dy = xiS[nb * 3 + 1] - xj[1];
        float dz = xiS[nb * 3 + 2] - xj[2];
        xdS[t * 3 + 0] = dx; xdS[t * 3 + 1] = dy; xdS[t * 3 + 2] = dz;
        sqdS[t] = dx * dx + dy * dy + dz * dz;
    }
    // gather h_neigh, transposed into hjT[nb][channel][k]
    for (int e = half; e < NPB * KK; e += 2) {
        int j  = idxS[e];
        int nb = e >> 4, k = e & 15;
        const float* hj = h + (base_bn + j) * HH;
#pragma unroll
        for (int r = 0; r < 4; ++r)
            hjT[(nb * HH + lane + 32 * r) * PADK + k] = hj[lane + 32 * r];
    }
    __syncthreads();

    const float* bp0 = hjT + (2 * half) * HH * PADK;
    const float* bp1 = hjT + (2 * half + 1) * HH * PADK;
    const float* mp0 = m1T + (2 * half) * HH * PADK;
    const float* mp1 = m1T + (2 * half + 1) * HH * PADK;

    // ---- s_i = h_i @ We1[0:128, cols]  (k-invariant part of layer 1) ----
    ull s[4] = {0ull, 0ull, 0ull, 0ull};
    {
        const float* Wb = We1 + lane;
#pragma unroll 8
        for (int i = 0; i < HH; ++i) {
            ull hv = *(const ull*)(hiS + i * 4 + 2 * half);
#pragma unroll
            for (int c = 0; c < 4; ++c) fma2(s[c], hv, pk2(Wb[i * HH + 32 * c]));
        }
    }

    ull acc[2][8][4];

    // ---- layer 1: m1 = silu(feat @ We1 + be1) ----
#pragma unroll
    for (int n_ = 0; n_ < 2; ++n_)
#pragma unroll
        for (int q = 0; q < 8; ++q)
#pragma unroll
            for (int c = 0; c < 4; ++c) acc[n_][q][c] = 0ull;
    gemm4(bp0, bp1, We1 + 128 * HH + lane, acc);
    {
        float b1v[4], wsq[4];
        float sif[4][2];
#pragma unroll
        for (int c = 0; c < 4; ++c) {
            b1v[c] = be1[lane + 32 * c];
            wsq[c] = We1[256 * HH + lane + 32 * c];
            float2 sv = up2(s[c]); sif[c][0] = sv.x; sif[c][1] = sv.y;
        }
#pragma unroll
        for (int nbl = 0; nbl < 2; ++nbl) {
            int nb = 2 * half + nbl;
#pragma unroll
            for (int c = 0; c < 4; ++c) {
                float outk[16];
#pragma unroll
                for (int kp = 0; kp < 8; ++kp) {
                    float2 v = up2(acc[nbl][kp][c]);
                    int k0 = kp * 2;
                    outk[k0]     = silu_f(v.x + sif[c][nbl] + b1v[c] + sqdS[nb * 16 + k0] * wsq[c]);
                    outk[k0 + 1] = silu_f(v.y + sif[c][nbl] + b1v[c] + sqdS[nb * 16 + k0 + 1] * wsq[c]);
                }
                float* dst = m1T + (nb * HH + lane + 32 * c) * PADK;
#pragma unroll
                for (int q = 0; q < 4; ++q)
                    *(float4*)(dst + q * 4) =
                        make_float4(outk[q*4], outk[q*4+1], outk[q*4+2], outk[q*4+3]);
            }
        }
    }
    __syncthreads();

    // ---- layer 2: m_ij = silu(m1 @ We2 + be2); m_i = sum_k m_ij ----
#pragma unroll
    for (int n_ = 0; n_ < 2; ++n_)
#pragma unroll
        for (int q = 0; q < 8; ++q)
#pragma unroll
            for (int c = 0; c < 4; ++c) acc[n_][q][c] = 0ull;
    gemm4(mp0, mp1, We2 + lane, acc);
    {
        float b2v[4];
#pragma unroll
        for (int c = 0; c < 4; ++c) b2v[c] = be2[lane + 32 * c];
#pragma unroll
        for (int nbl = 0; nbl < 2; ++nbl) {
            int nb = 2 * half + nbl;
#pragma unroll
            for (int c = 0; c < 4; ++c) {
                float outk[16];
                float ssum = 0.0f;
#pragma unroll
                for (int kp = 0; kp < 8; ++kp) {
                    float2 v = up2(acc[nbl][kp][c]);
                    int k0 = kp * 2;
                    float m0  = silu_f(v.x + b2v[c]);
                    float m1v = silu_f(v.y + b2v[c]);
                    outk[k0] = m0; outk[k0 + 1] = m1v;
                    ssum += m0 + m1v;
                }
                float* dst = hjT + (nb * HH + lane + 32 * c) * PADK;  // reuse hjT
#pragma unroll
                for (int q = 0; q < 4; ++q)
                    *(float4*)(dst + q * 4) =
                        make_float4(outk[q*4], outk[q*4+1], outk[q*4+2], outk[q*4+3]);
                miS[(lane + 32 * c) * 4 + nb] = ssum;
            }
        }
    }
    __syncthreads();

    // ---- layer 3: c1 = silu(m_ij @ Wc1 + bc1); partials of c1 @ Wc2 ----
#pragma unroll
    for (int n_ = 0; n_ < 2; ++n_)
#pragma unroll
        for (int q = 0; q < 8; ++q)
#pragma unroll
            for (int c = 0; c < 4; ++c) acc[n_][q][c] = 0ull;
    gemm4(bp0, bp1, Wc1 + lane, acc);
    {
        float b3v[4], w2v[4];
#pragma unroll
        for (int c = 0; c < 4; ++c) {
            b3v[c] = bc1[lane + 32 * c];
            w2v[c] = Wc2[lane + 32 * c];
        }
#pragma unroll
        for (int nbl = 0; nbl < 2; ++nbl) {
            int nb = 2 * half + nbl;
#pragma unroll
            for (int c = 0; c < 4; ++c) {
#pragma unroll
                for (int kp = 0; kp < 8; ++kp) {
                    float2 v = up2(acc[nbl][kp][c]);
                    int e0 = nb * 16 + kp * 2;
                    prS[e0 * 129 + lane + 32 * c]       = silu_f(v.x + b3v[c]) * w2v[c];
                    prS[(e0 + 1) * 129 + lane + 32 * c] = silu_f(v.y + b3v[c]) * w2v[c];
                }
            }
        }
    }
    __syncthreads();

    // reduce coord_w over the 128 channels (each thread: one edge row)
    {
        const float* row = prS + t * 129;
        float ssum = 0.0f;
#pragma unroll 8
        for (int i = 0; i < HH; ++i) ssum += row[i];
        cwS[t] = ssum;
    }
    __syncthreads();

    // x_new
    if (t < NPB * 3) {
        int nb = t / 3, d = t % 3;
        float ssum = 0.0f;
#pragma unroll
        for (int k = 0; k < KK; ++k)
            ssum += xdS[(nb * 16 + k) * 3 + d] * cwS[nb * 16 + k];
        out[(long)NB_ * NN * HH + (base_bn + n0 + nb) * 3 + d] =
            xiS[t] + ssum * (1.0f / 16.0f);
    }

    // ---- node MLP layer 1 ----
    ull a[4] = {0ull, 0ull, 0ull, 0ull};
    {
        const float* W1h = Wn1 + lane;
        const float* W1m = Wn1 + 128 * HH + lane;
#pragma unroll 4
        for (int i = 0; i < HH; ++i) {
            ull hv = *(const ull*)(hiS + i * 4 + 2 * half);
            ull mv = *(const ull*)(miS + i * 4 + 2 * half);
#pragma unroll
            for (int c = 0; c < 4; ++c) {
                fma2(a[c], hv, pk2(W1h[i * HH + 32 * c]));
                fma2(a[c], mv, pk2(W1m[i * HH + 32 * c]));
            }
        }
    }
    {
#pragma unroll
        for (int c = 0; c < 4; ++c) {
            float bnv = bn1[lane + 32 * c];
            float2 u = up2(a[c]);
            *(float2*)(n1S + (lane + 32 * c) * 4 + 2 * half) =
                make_float2(silu_f(u.x + bnv), silu_f(u.y + bnv));
        }
    }
    __syncthreads();

    // ---- node MLP layer 2 ----
    ull a2[4] = {0ull, 0ull, 0ull, 0ull};
    {
        const float* W2 = Wn2 + lane;
#pragma unroll 8
        for (int i = 0; i < HH; ++i) {
            ull nv = *(const ull*)(n1S + i * 4 + 2 * half);
#pragma unroll
            for (int c = 0; c < 4; ++c) fma2(a2[c], nv, pk2(W2[i * HH + 32 * c]));
        }
    }
    {
#pragma unroll
        for (int c = 0; c < 4; ++c) {
            int col = lane + 32 * c;
            float bv = bn2[col];
            float2 u = up2(a2[c]);
            int nb0 = 2 * half;
            out[(base_bn + n0 + nb0) * HH + col]     = u.x + bv + hiS[col * 4 + nb0];
            out[(base_bn + n0 + nb0 + 1) * HH + col] = u.y + bv + hiS[col * 4 + nb0 + 1];
        }
    }
}

extern "C" void kernel_launch(void* const* d_in, const int* in_sizes, int n_in,
                              void* d_out, int out_size) {
    const float* h   = (const float*)d_in[0];
    const float* x   = (const float*)d_in[1];
    const int*   ei  = (const int*)d_in[2];
    const float* We1 = (const float*)d_in[3];
    const float* be1 = (const float*)d_in[4];
    const float* We2 = (const float*)d_in[5];
    const float* be2 = (const float*)d_in[6];
    const float* Wc1 = (const float*)d_in[7];
    const float* bc1 = (const float*)d_in[8];
    const float* Wc2 = (const float*)d_in[9];
    const float* Wn1 = (const float*)d_in[10];
    const float* bn1 = (const float*)d_in[11];
    const float* Wn2 = (const float*)d_in[12];
    const float* bn2 = (const float*)d_in[13];
    float* out = (float*)d_out;

    cudaFuncSetAttribute(egnn_kernel, cudaFuncAttributeMaxDynamicSharedMemorySize,
                         SMEM_BYTES);
    dim3 grid(NB_ * NN / NPB);   // 8192 blocks
    egnn_kernel<<<grid, NTH, SMEM_BYTES>>>(h, x, ei, We1, be1, We2, be2,
                                           Wc1, bc1, Wc2, Wn1, bn1, Wn2, bn2, out);
}

// round 3
// speedup vs baseline: 1.6420x; 1.6420x over previous
#include <cuda_runtime.h>

// EGNN layer, fused per-node kernel, round 3.
// B=2, N=16384, K=16, H=128.
// Block = 4 nodes, 128 threads (4 warps). Warp w owns node w; lane owns
// contiguous output columns 4*lane..4*lane+3 (weight loads = LDG.128).
// 2 blocks/SM -> 2 warps/SMSP for latency hiding.
// Each broadcast LDS.128 feeds 8 FFMA2 (fp32x2 packed FMA).

#define HH   128
#define NB_  2
#define NN   16384
#define KK   16
#define NPB  4
#define PADK 20
#define NTH  128

typedef unsigned long long ull;

__device__ __forceinline__ ull pk2(float w) {
    ull r; asm("mov.b64 %0, {%1, %1};" : "=l"(r) : "f"(w)); return r;
}
__device__ __forceinline__ ull pkf(float a, float b) {
    ull r; asm("mov.b64 %0, {%1, %2};" : "=l"(r) : "f"(a), "f"(b)); return r;
}
__device__ __forceinline__ void fma2(ull &d, ull a, ull b) {
    asm("fma.rn.f32x2 %0, %1, %2, %0;" : "+l"(d) : "l"(a), "l"(b));
}
__device__ __forceinline__ float2 up2(ull v) {
    float2 f; asm("mov.b64 {%0, %1}, %2;" : "=f"(f.x), "=f"(f.y) : "l"(v)); return f;
}
__device__ __forceinline__ float silu_f(float v) { return v / (1.0f + __expf(-v)); }

// Shared-memory float offsets
#define OFF_HJT 0            // NPB*128*PADK = 10240 floats (holds m_ijT in phase 3)
#define OFF_M1T 10240        // 10240 floats (also prS [64][129] in coord reduce)
#define OFF_HIS 20480        // 512 floats, layout [channel][nb]
#define OFF_MIS 20992        // 512 floats, layout [channel][nb]
#define OFF_N1S 21504        // 512 floats, layout [channel][nb]
#define OFF_SQD 22016        // 64
#define OFF_XD  22080        // 192  [nb][k][d]
#define OFF_XI  22272        // 16 (12 used)
#define OFF_CW  22288        // 64
#define OFF_IDX 22352        // 64 ints
#define SMEM_FLOATS 22416
#define SMEM_BYTES (SMEM_FLOATS * 4)

// rowbase: smem [128][PADK] for this warp's node. Wq = W + 4*lane
// (4 contiguous columns -> one LDG.128 per row). acc[kp][c] packs
// k-pair (2kp, 2kp+1).
__device__ __forceinline__ void gemm_n(const float* __restrict__ rowbase,
                                       const float* __restrict__ Wq,
                                       ull (&acc)[8][4]) {
    float4 wcur[4];
#pragma unroll
    for (int q = 0; q < 4; ++q) wcur[q] = *(const float4*)(Wq + q * HH);

#pragma unroll 1
    for (int ib = 0; ib < HH; ib += 4) {
        float4 wn[4];
#pragma unroll
        for (int q = 0; q < 4; ++q) wn[q] = make_float4(0.f, 0.f, 0.f, 0.f);
        if (ib + 4 < HH) {
#pragma unroll
            for (int q = 0; q < 4; ++q)
                wn[q] = *(const float4*)(Wq + (ib + 4 + q) * HH);
        }
#pragma unroll
        for (int q = 0; q < 4; ++q) {
            const float* bp = rowbase + (ib + q) * PADK;
            ulonglong2 v0 = *(const ulonglong2*)(bp);
            ulonglong2 v1 = *(const ulonglong2*)(bp + 4);
            ulonglong2 v2 = *(const ulonglong2*)(bp + 8);
            ulonglong2 v3 = *(const ulonglong2*)(bp + 12);
            float4 w = wcur[q];
            ull wp[4] = {pk2(w.x), pk2(w.y), pk2(w.z), pk2(w.w)};
#pragma unroll
            for (int c = 0; c < 4; ++c) {
                fma2(acc[0][c], v0.x, wp[c]);
                fma2(acc[1][c], v0.y, wp[c]);
                fma2(acc[2][c], v1.x, wp[c]);
                fma2(acc[3][c], v1.y, wp[c]);
                fma2(acc[4][c], v2.x, wp[c]);
                fma2(acc[5][c], v2.y, wp[c]);
                fma2(acc[6][c], v3.x, wp[c]);
                fma2(acc[7][c], v3.y, wp[c]);
            }
        }
#pragma unroll
        for (int q = 0; q < 4; ++q) wcur[q] = wn[q];
    }
}

__global__ void __launch_bounds__(NTH, 2)
egnn_kernel(const float* __restrict__ h, const float* __restrict__ x,
            const int* __restrict__ eidx,
            const float* __restrict__ We1, const float* __restrict__ be1,
            const float* __restrict__ We2, const float* __restrict__ be2,
            const float* __restrict__ Wc1, const float* __restrict__ bc1,
            const float* __restrict__ Wc2,
            const float* __restrict__ Wn1, const float* __restrict__ bn1,
            const float* __restrict__ Wn2, const float* __restrict__ bn2,
            float* __restrict__ out) {
    extern __shared__ float sm[];
    float* hjT  = sm + OFF_HJT;
    float* m1T  = sm + OFF_M1T;
    float* prS  = sm + OFF_M1T;   // reuse: [64][129]
    float* hiS  = sm + OFF_HIS;
    float* miS  = sm + OFF_MIS;
    float* n1S  = sm + OFF_N1S;
    float* sqdS = sm + OFF_SQD;
    float* xdS  = sm + OFF_XD;
    float* xiS  = sm + OFF_XI;
    float* cwS  = sm + OFF_CW;
    int*   idxS = (int*)(sm + OFF_IDX);

    const int t    = threadIdx.x;
    const int nb   = t >> 5;       // warp = node
    const int lane = t & 31;
    const int cb   = lane * 4;     // 4 contiguous output columns
    const int g    = blockIdx.x;
    const int b    = g >> 12;      // 4096 groups per batch
    const int n0   = (g & 4095) * NPB;
    const long base_bn = (long)b * NN;

    // ---- stage inputs ----
    if (t < NPB * KK) idxS[t] = eidx[(base_bn + n0 + (t >> 4)) * KK + (t & 15)];
    if (t < NPB * 3)  xiS[t]  = x[(base_bn + n0 + t / 3) * 3 + (t % 3)];
    {
        float4 hv;
        hv.x = h[(base_bn + n0 + 0) * HH + t];
        hv.y = h[(base_bn + n0 + 1) * HH + t];
        hv.z = h[(base_bn + n0 + 2) * HH + t];
        hv.w = h[(base_bn + n0 + 3) * HH + t];
        *(float4*)(hiS + t * 4) = hv;
    }
    __syncthreads();

    // x_diff / sq_dist per edge (64 edges)
    if (t < NPB * KK) {
        int j  = idxS[t];
        int en = t >> 4;
        const float* xj = x + (base_bn + j) * 3;
        float dx = xiS[en * 3 + 0] - xj[0];
        float dy = xiS[en * 3 + 1] - xj[1];
        float dz = xiS[en * 3 + 2] - xj[2];
        xdS[t * 3 + 0] = dx; xdS[t * 3 + 1] = dy; xdS[t * 3 + 2] = dz;
        sqdS[t] = dx * dx + dy * dy + dz * dz;
    }
    // gather h_neigh, transposed into hjT[node][channel][k]
    for (int e = nb; e < NPB * KK; e += 4) {
        int j  = idxS[e];
        int en = e >> 4, k = e & 15;
        const float* hj = h + (base_bn + j) * HH;
#pragma unroll
        for (int r = 0; r < 4; ++r)
            hjT[(en * HH + lane + 32 * r) * PADK + k] = hj[lane + 32 * r];
    }
    __syncthreads();

    const float* rowH = hjT + nb * HH * PADK;
    const float* rowM = m1T + nb * HH * PADK;

    // ---- s_i = h_i @ We1[0:128, cols]  (k-invariant part of layer 1) ----
    ull s01 = 0ull, s23 = 0ull;
    {
        const float* Wq = We1 + cb;
#pragma unroll 8
        for (int i = 0; i < HH; ++i) {
            ull hp = pk2(hiS[i * 4 + nb]);
            float4 w = *(const float4*)(Wq + i * HH);
            fma2(s01, hp, pkf(w.x, w.y));
            fma2(s23, hp, pkf(w.z, w.w));
        }
    }

    ull acc[8][4];

    // ---- layer 1: m1 = silu(feat @ We1 + be1) ----
#pragma unroll
    for (int q = 0; q < 8; ++q)
#pragma unroll
        for (int c = 0; c < 4; ++c) acc[q][c] = 0ull;
    gemm_n(rowH, We1 + 128 * HH + cb, acc);
    {
        float4 b1v = *(const float4*)(be1 + cb);
        float4 wsq = *(const float4*)(We1 + 256 * HH + cb);
        float2 u01 = up2(s01), u23 = up2(s23);
        float sif[4] = {u01.x, u01.y, u23.x, u23.y};
        float b1a[4] = {b1v.x, b1v.y, b1v.z, b1v.w};
        float wsa[4] = {wsq.x, wsq.y, wsq.z, wsq.w};
#pragma unroll
        for (int c = 0; c < 4; ++c) {
            float outk[16];
#pragma unroll
            for (int kp = 0; kp < 8; ++kp) {
                float2 v = up2(acc[kp][c]);
                int k0 = kp * 2;
                outk[k0]     = silu_f(v.x + sif[c] + b1a[c] + sqdS[nb * 16 + k0] * wsa[c]);
                outk[k0 + 1] = silu_f(v.y + sif[c] + b1a[c] + sqdS[nb * 16 + k0 + 1] * wsa[c]);
            }
            float* dst = m1T + (nb * HH + cb + c) * PADK;
#pragma unroll
            for (int q = 0; q < 4; ++q)
                *(float4*)(dst + q * 4) =
                    make_float4(outk[q*4], outk[q*4+1], outk[q*4+2], outk[q*4+3]);
        }
    }
    __syncthreads();

    // ---- layer 2: m_ij = silu(m1 @ We2 + be2); m_i = sum_k m_ij ----
#pragma unroll
    for (int q = 0; q < 8; ++q)
#pragma unroll
        for (int c = 0; c < 4; ++c) acc[q][c] = 0ull;
    gemm_n(rowM, We2 + cb, acc);
    {
        float4 b2v = *(const float4*)(be2 + cb);
        float b2a[4] = {b2v.x, b2v.y, b2v.z, b2v.w};
#pragma unroll
        for (int c = 0; c < 4; ++c) {
            float outk[16];
            float ssum = 0.0f;
#pragma unroll
            for (int kp = 0; kp < 8; ++kp) {
                float2 v = up2(acc[kp][c]);
                int k0 = kp * 2;
                float m0  = silu_f(v.x + b2a[c]);
                float m1v = silu_f(v.y + b2a[c]);
                outk[k0] = m0; outk[k0 + 1] = m1v;
                ssum += m0 + m1v;
            }
            float* dst = hjT + (nb * HH + cb + c) * PADK;   // reuse hjT for m_ijT
#pragma unroll
            for (int q = 0; q < 4; ++q)
                *(float4*)(dst + q * 4) =
                    make_float4(outk[q*4], outk[q*4+1], outk[q*4+2], outk[q*4+3]);
            miS[(cb + c) * 4 + nb] = ssum;
        }
    }
    __syncthreads();

    // ---- layer 3: c1 = silu(m_ij @ Wc1 + bc1); partials of c1 @ Wc2 ----
#pragma unroll
    for (int q = 0; q < 8; ++q)
#pragma unroll
        for (int c = 0; c < 4; ++c) acc[q][c] = 0ull;
    gemm_n(rowH, Wc1 + cb, acc);
    {
        float4 b3v = *(const float4*)(bc1 + cb);
        float4 w2v = *(const float4*)(Wc2 + cb);
        float b3a[4] = {b3v.x, b3v.y, b3v.z, b3v.w};
        float w2a[4] = {w2v.x, w2v.y, w2v.z, w2v.w};
#pragma unroll
        for (int c = 0; c < 4; ++c) {
#pragma unroll
            for (int kp = 0; kp < 8; ++kp) {
                float2 v = up2(acc[kp][c]);
                int e0 = nb * 16 + kp * 2;
                prS[e0 * 129 + cb + c]       = silu_f(v.x + b3a[c]) * w2a[c];
                prS[(e0 + 1) * 129 + cb + c] = silu_f(v.y + b3a[c]) * w2a[c];
            }
        }
    }
    __syncthreads();

    // reduce coord_w over the 128 channels (first 64 threads: one edge each)
    if (t < NPB * KK) {
        const float* row = prS + t * 129;
        float ssum = 0.0f;
#pragma unroll 8
        for (int i = 0; i < HH; ++i) ssum += row[i];
        cwS[t] = ssum;
    }
    __syncthreads();

    // x_new
    if (t < NPB * 3) {
        int en = t / 3, d = t % 3;
        float ssum = 0.0f;
#pragma unroll
        for (int k = 0; k < KK; ++k)
            ssum += xdS[(en * 16 + k) * 3 + d] * cwS[en * 16 + k];
        out[(long)NB_ * NN * HH + (base_bn + n0 + en) * 3 + d] =
            xiS[t] + ssum * (1.0f / 16.0f);
    }

    // ---- node MLP layer 1: silu([h_i, m_i] @ Wn1 + bn1) ----
    ull a01 = 0ull, a23 = 0ull;
    {
        const float* W1h = Wn1 + cb;
        const float* W1m = Wn1 + 128 * HH + cb;
#pragma unroll 4
        for (int i = 0; i < HH; ++i) {
            ull hp = pk2(hiS[i * 4 + nb]);
            ull mp = pk2(miS[i * 4 + nb]);
            float4 w1 = *(const float4*)(W1h + i * HH);
            float4 w2 = *(const float4*)(W1m + i * HH);
            fma2(a01, hp, pkf(w1.x, w1.y));
            fma2(a23, hp, pkf(w1.z, w1.w));
            fma2(a01, mp, pkf(w2.x, w2.y));
            fma2(a23, mp, pkf(w2.z, w2.w));
        }
    }
    {
        float4 bv = *(const float4*)(bn1 + cb);
        float2 u01 = up2(a01), u23 = up2(a23);
        n1S[(cb + 0) * 4 + nb] = silu_f(u01.x + bv.x);
        n1S[(cb + 1) * 4 + nb] = silu_f(u01.y + bv.y);
        n1S[(cb + 2) * 4 + nb] = silu_f(u23.x + bv.z);
        n1S[(cb + 3) * 4 + nb] = silu_f(u23.y + bv.w);
    }
    __syncthreads();

    // ---- node MLP layer 2 + residual ----
    a01 = 0ull; a23 = 0ull;
    {
        const float* W2 = Wn2 + cb;
#pragma unroll 8
        for (int i = 0; i < HH; ++i) {
            ull np = pk2(n1S[i * 4 + nb]);
            float4 w = *(const float4*)(W2 + i * HH);
            fma2(a01, np, pkf(w.x, w.y));
            fma2(a23, np, pkf(w.z, w.w));
        }
    }
    {
        float4 bv = *(const float4*)(bn2 + cb);
        float2 u01 = up2(a01), u23 = up2(a23);
        float4 res;
        res.x = u01.x + bv.x + hiS[(cb + 0) * 4 + nb];
        res.y = u01.y + bv.y + hiS[(cb + 1) * 4 + nb];
        res.z = u23.x + bv.z + hiS[(cb + 2) * 4 + nb];
        res.w = u23.y + bv.w + hiS[(cb + 3) * 4 + nb];
        *(float4*)(out + (base_bn + n0 + nb) * HH + cb) = res;
    }
}

extern "C" void kernel_launch(void* const* d_in, const int* in_sizes, int n_in,
                              void* d_out, int out_size) {
    const float* h   = (const float*)d_in[0];
    const float* x   = (const float*)d_in[1];
    const int*   ei  = (const int*)d_in[2];
    const float* We1 = (const float*)d_in[3];
    const float* be1 = (const float*)d_in[4];
    const float* We2 = (const float*)d_in[5];
    const float* be2 = (const float*)d_in[6];
    const float* Wc1 = (const float*)d_in[7];
    const float* bc1 = (const float*)d_in[8];
    const float* Wc2 = (const float*)d_in[9];
    const float* Wn1 = (const float*)d_in[10];
    const float* bn1 = (const float*)d_in[11];
    const float* Wn2 = (const float*)d_in[12];
    const float* bn2 = (const float*)d_in[13];
    float* out = (float*)d_out;

    cudaFuncSetAttribute(egnn_kernel, cudaFuncAttributeMaxDynamicSharedMemorySize,
                         SMEM_BYTES);
    dim3 grid(NB_ * NN / NPB);   // 8192 blocks
    egnn_kernel<<<grid, NTH, SMEM_BYTES>>>(h, x, ei, We1, be1, We2, be2,
                                           Wc1, bc1, Wc2, Wn1, bn1, Wn2, bn2, out);
}

// round 4
// speedup vs baseline: 1.6429x; 1.0005x over previous
#include <cuda_runtime.h>

// EGNN layer, fused per-node kernel, round 4.
// Round 3 + explicit software pipelining in the edge GEMMs:
//   B-row (smem) prefetched 1 row ahead, weight row (gmem) prefetched 4 ahead,
//   so LDS(29cyc)/LDG(~234cyc L2) latencies are covered by the FFMA2 block.

#define HH   128
#define NB_  2
#define NN   16384
#define KK   16
#define NPB  4
#define PADK 20
#define NTH  128

typedef unsigned long long ull;

__device__ __forceinline__ ull pk2(float w) {
    ull r; asm("mov.b64 %0, {%1, %1};" : "=l"(r) : "f"(w)); return r;
}
__device__ __forceinline__ ull pkf(float a, float b) {
    ull r; asm("mov.b64 %0, {%1, %2};" : "=l"(r) : "f"(a), "f"(b)); return r;
}
__device__ __forceinline__ void fma2(ull &d, ull a, ull b) {
    asm("fma.rn.f32x2 %0, %1, %2, %0;" : "+l"(d) : "l"(a), "l"(b));
}
__device__ __forceinline__ float2 up2(ull v) {
    float2 f; asm("mov.b64 {%0, %1}, %2;" : "=f"(f.x), "=f"(f.y) : "l"(v)); return f;
}
__device__ __forceinline__ float silu_f(float v) { return v / (1.0f + __expf(-v)); }

// Shared-memory float offsets
#define OFF_HJT 0            // NPB*128*PADK = 10240 floats (holds m_ijT in phase 3)
#define OFF_M1T 10240        // 10240 floats (also prS [64][129] in coord reduce)
#define OFF_HIS 20480        // 512 floats, layout [channel][nb]
#define OFF_MIS 20992        // 512 floats, layout [channel][nb]
#define OFF_N1S 21504        // 512 floats, layout [channel][nb]
#define OFF_SQD 22016        // 64
#define OFF_XD  22080        // 192  [nb][k][d]
#define OFF_XI  22272        // 16 (12 used)
#define OFF_CW  22288        // 64
#define OFF_IDX 22352        // 64 ints
#define SMEM_FLOATS 22416
#define SMEM_BYTES (SMEM_FLOATS * 4)

// rowbase: smem [128][PADK] for this warp's node (over-read of 1 row past the
// end stays inside the dynamic smem allocation). Wq = W + 4*lane (4 contiguous
// columns -> LDG.128 per row). acc[kp][c] packs k-pair (2kp, 2kp+1).
// Pipeline: B one row ahead (registers), W four rows ahead (registers).
__device__ __forceinline__ void gemm_n(const float* __restrict__ rowbase,
                                       const float* __restrict__ Wq,
                                       ull (&acc)[8][4]) {
    float4 wbuf[4];
#pragma unroll
    for (int q = 0; q < 4; ++q) wbuf[q] = *(const float4*)(Wq + q * HH);

    // current B row (row 0)
    ulonglong2 c0 = *(const ulonglong2*)(rowbase);
    ulonglong2 c1 = *(const ulonglong2*)(rowbase + 4);
    ulonglong2 c2 = *(const ulonglong2*)(rowbase + 8);
    ulonglong2 c3 = *(const ulonglong2*)(rowbase + 12);

    const float* bp = rowbase + PADK;       // next B row to fetch

#pragma unroll 1
    for (int ib = 0; ib < HH; ib += 4) {
        // weight prefetch source: rows ib+4..ib+7, or wrap to row 0 on last
        // iteration (branch-free; values unused)
        const float* wpre = (ib + 4 < HH) ? (Wq + (ib + 4) * HH) : Wq;
        float4 wn[4];
#pragma unroll
        for (int q = 0; q < 4; ++q) {
            // 1) prefetch next weight row
            wn[q] = *(const float4*)(wpre + q * HH);
            // 2) prefetch next B row (over-reads one row at the very end;
            //    stays inside the smem allocation, value unused)
            ulonglong2 n0 = *(const ulonglong2*)(bp);
            ulonglong2 n1 = *(const ulonglong2*)(bp + 4);
            ulonglong2 n2 = *(const ulonglong2*)(bp + 8);
            ulonglong2 n3 = *(const ulonglong2*)(bp + 12);
            bp += PADK;
            // 3) compute current row
            float4 w = wbuf[q];
            ull wp0 = pk2(w.x), wp1 = pk2(w.y), wp2 = pk2(w.z), wp3 = pk2(w.w);
            fma2(acc[0][0], c0.x, wp0); fma2(acc[0][1], c0.x, wp1);
            fma2(acc[0][2], c0.x, wp2); fma2(acc[0][3], c0.x, wp3);
            fma2(acc[1][0], c0.y, wp0); fma2(acc[1][1], c0.y, wp1);
            fma2(acc[1][2], c0.y, wp2); fma2(acc[1][3], c0.y, wp3);
            fma2(acc[2][0], c1.x, wp0); fma2(acc[2][1], c1.x, wp1);
            fma2(acc[2][2], c1.x, wp2); fma2(acc[2][3], c1.x, wp3);
            fma2(acc[3][0], c1.y, wp0); fma2(acc[3][1], c1.y, wp1);
            fma2(acc[3][2], c1.y, wp2); fma2(acc[3][3], c1.y, wp3);
            fma2(acc[4][0], c2.x, wp0); fma2(acc[4][1], c2.x, wp1);
            fma2(acc[4][2], c2.x, wp2); fma2(acc[4][3], c2.x, wp3);
            fma2(acc[5][0], c2.y, wp0); fma2(acc[5][1], c2.y, wp1);
            fma2(acc[5][2], c2.y, wp2); fma2(acc[5][3], c2.y, wp3);
            fma2(acc[6][0], c3.x, wp0); fma2(acc[6][1], c3.x, wp1);
            fma2(acc[6][2], c3.x, wp2); fma2(acc[6][3], c3.x, wp3);
            fma2(acc[7][0], c3.y, wp0); fma2(acc[7][1], c3.y, wp1);
            fma2(acc[7][2], c3.y, wp2); fma2(acc[7][3], c3.y, wp3);
            // rotate B
            c0 = n0; c1 = n1; c2 = n2; c3 = n3;
        }
#pragma unroll
        for (int q = 0; q < 4; ++q) wbuf[q] = wn[q];
    }
}

__global__ void __launch_bounds__(NTH, 2)
egnn_kernel(const float* __restrict__ h, const float* __restrict__ x,
            const int* __restrict__ eidx,
            const float* __restrict__ We1, const float* __restrict__ be1,
            const float* __restrict__ We2, const float* __restrict__ be2,
            const float* __restrict__ Wc1, const float* __restrict__ bc1,
            const float* __restrict__ Wc2,
            const float* __restrict__ Wn1, const float* __restrict__ bn1,
            const float* __restrict__ Wn2, const float* __restrict__ bn2,
            float* __restrict__ out) {
    extern __shared__ float sm[];
    float* hjT  = sm + OFF_HJT;
    float* m1T  = sm + OFF_M1T;
    float* prS  = sm + OFF_M1T;   // reuse: [64][129]
    float* hiS  = sm + OFF_HIS;
    float* miS  = sm + OFF_MIS;
    float* n1S  = sm + OFF_N1S;
    float* sqdS = sm + OFF_SQD;
    float* xdS  = sm + OFF_XD;
    float* xiS  = sm + OFF_XI;
    float* cwS  = sm + OFF_CW;
    int*   idxS = (int*)(sm + OFF_IDX);

    const int t    = threadIdx.x;
    const int nb   = t >> 5;       // warp = node
    const int lane = t & 31;
    const int cb   = lane * 4;     // 4 contiguous output columns
    const int g    = blockIdx.x;
    const int b    = g >> 12;      // 4096 groups per batch
    const int n0   = (g & 4095) * NPB;
    const long base_bn = (long)b * NN;

    // ---- stage inputs ----
    if (t < NPB * KK) idxS[t] = eidx[(base_bn + n0 + (t >> 4)) * KK + (t & 15)];
    if (t < NPB * 3)  xiS[t]  = x[(base_bn + n0 + t / 3) * 3 + (t % 3)];
    {
        float4 hv;
        hv.x = h[(base_bn + n0 + 0) * HH + t];
        hv.y = h[(base_bn + n0 + 1) * HH + t];
        hv.z = h[(base_bn + n0 + 2) * HH + t];
        hv.w = h[(base_bn + n0 + 3) * HH + t];
        *(float4*)(hiS + t * 4) = hv;
    }
    __syncthreads();

    // x_diff / sq_dist per edge (64 edges)
    if (t < NPB * KK) {
        int j  = idxS[t];
        int en = t >> 4;
        const float* xj = x + (base_bn + j) * 3;
        float dx = xiS[en * 3 + 0] - xj[0];
        float dy = xiS[en * 3 + 1] - xj[1];
        float dz = xiS[en * 3 + 2] - xj[2];
        xdS[t * 3 + 0] = dx; xdS[t * 3 + 1] = dy; xdS[t * 3 + 2] = dz;
        sqdS[t] = dx * dx + dy * dy + dz * dz;
    }
    // gather h_neigh, transposed into hjT[node][channel][k]
    for (int e = nb; e < NPB * KK; e += 4) {
        int j  = idxS[e];
        int en = e >> 4, k = e & 15;
        const float* hj = h + (base_bn + j) * HH;
#pragma unroll
        for (int r = 0; r < 4; ++r)
            hjT[(en * HH + lane + 32 * r) * PADK + k] = hj[lane + 32 * r];
    }
    __syncthreads();

    const float* rowH = hjT + nb * HH * PADK;
    const float* rowM = m1T + nb * HH * PADK;

    // ---- s_i = h_i @ We1[0:128, cols]  (k-invariant part of layer 1) ----
    ull s01 = 0ull, s23 = 0ull;
    {
        const float* Wq = We1 + cb;
#pragma unroll 8
        for (int i = 0; i < HH; ++i) {
            ull hp = pk2(hiS[i * 4 + nb]);
            float4 w = *(const float4*)(Wq + i * HH);
            fma2(s01, hp, pkf(w.x, w.y));
            fma2(s23, hp, pkf(w.z, w.w));
        }
    }

    ull acc[8][4];

    // ---- layer 1: m1 = silu(feat @ We1 + be1) ----
#pragma unroll
    for (int q = 0; q < 8; ++q)
#pragma unroll
        for (int c = 0; c < 4; ++c) acc[q][c] = 0ull;
    gemm_n(rowH, We1 + 128 * HH + cb, acc);
    {
        float4 b1v = *(const float4*)(be1 + cb);
        float4 wsq = *(const float4*)(We1 + 256 * HH + cb);
        float2 u01 = up2(s01), u23 = up2(s23);
        float sif[4] = {u01.x, u01.y, u23.x, u23.y};
        float b1a[4] = {b1v.x, b1v.y, b1v.z, b1v.w};
        float wsa[4] = {wsq.x, wsq.y, wsq.z, wsq.w};
#pragma unroll
        for (int c = 0; c < 4; ++c) {
            float outk[16];
#pragma unroll
            for (int kp = 0; kp < 8; ++kp) {
                float2 v = up2(acc[kp][c]);
                int k0 = kp * 2;
                outk[k0]     = silu_f(v.x + sif[c] + b1a[c] + sqdS[nb * 16 + k0] * wsa[c]);
                outk[k0 + 1] = silu_f(v.y + sif[c] + b1a[c] + sqdS[nb * 16 + k0 + 1] * wsa[c]);
            }
            float* dst = m1T + (nb * HH + cb + c) * PADK;
#pragma unroll
            for (int q = 0; q < 4; ++q)
                *(float4*)(dst + q * 4) =
                    make_float4(outk[q*4], outk[q*4+1], outk[q*4+2], outk[q*4+3]);
        }
    }
    __syncthreads();

    // ---- layer 2: m_ij = silu(m1 @ We2 + be2); m_i = sum_k m_ij ----
#pragma unroll
    for (int q = 0; q < 8; ++q)
#pragma unroll
        for (int c = 0; c < 4; ++c) acc[q][c] = 0ull;
    gemm_n(rowM, We2 + cb, acc);
    {
        float4 b2v = *(const float4*)(be2 + cb);
        float b2a[4] = {b2v.x, b2v.y, b2v.z, b2v.w};
#pragma unroll
        for (int c = 0; c < 4; ++c) {
            float outk[16];
            float ssum = 0.0f;
#pragma unroll
            for (int kp = 0; kp < 8; ++kp) {
                float2 v = up2(acc[kp][c]);
                int k0 = kp * 2;
                float m0  = silu_f(v.x + b2a[c]);
                float m1v = silu_f(v.y + b2a[c]);
                outk[k0] = m0; outk[k0 + 1] = m1v;
                ssum += m0 + m1v;
            }
            float* dst = hjT + (nb * HH + cb + c) * PADK;   // reuse hjT for m_ijT
#pragma unroll
            for (int q = 0; q < 4; ++q)
                *(float4*)(dst + q * 4) =
                    make_float4(outk[q*4], outk[q*4+1], outk[q*4+2], outk[q*4+3]);
            miS[(cb + c) * 4 + nb] = ssum;
        }
    }
    __syncthreads();

    // ---- layer 3: c1 = silu(m_ij @ Wc1 + bc1); partials of c1 @ Wc2 ----
#pragma unroll
    for (int q = 0; q < 8; ++q)
#pragma unroll
        for (int c = 0; c < 4; ++c) acc[q][c] = 0ull;
    gemm_n(rowH, Wc1 + cb, acc);
    {
        float4 b3v = *(const float4*)(bc1 + cb);
        float4 w2v = *(const float4*)(Wc2 + cb);
        float b3a[4] = {b3v.x, b3v.y, b3v.z, b3v.w};
        float w2a[4] = {w2v.x, w2v.y, w2v.z, w2v.w};
#pragma unroll
        for (int c = 0; c < 4; ++c) {
#pragma unroll
            for (int kp = 0; kp < 8; ++kp) {
                float2 v = up2(acc[kp][c]);
                int e0 = nb * 16 + kp * 2;
                prS[e0 * 129 + cb + c]       = silu_f(v.x + b3a[c]) * w2a[c];
                prS[(e0 + 1) * 129 + cb + c] = silu_f(v.y + b3a[c]) * w2a[c];
            }
        }
    }
    __syncthreads();

    // reduce coord_w over the 128 channels (first 64 threads: one edge each)
    if (t < NPB * KK) {
        const float* row = prS + t * 129;
        float ssum = 0.0f;
#pragma unroll 8
        for (int i = 0; i < HH; ++i) ssum += row[i];
        cwS[t] = ssum;
    }
    __syncthreads();

    // x_new
    if (t < NPB * 3) {
        int en = t / 3, d = t % 3;
        float ssum = 0.0f;
#pragma unroll
        for (int k = 0; k < KK; ++k)
            ssum += xdS[(en * 16 + k) * 3 + d] * cwS[en * 16 + k];
        out[(long)NB_ * NN * HH + (base_bn + n0 + en) * 3 + d] =
            xiS[t] + ssum * (1.0f / 16.0f);
    }

    // ---- node MLP layer 1: silu([h_i, m_i] @ Wn1 + bn1) ----
    ull a01 = 0ull, a23 = 0ull;
    {
        const float* W1h = Wn1 + cb;
        const float* W1m = Wn1 + 128 * HH + cb;
#pragma unroll 4
        for (int i = 0; i < HH; ++i) {
            ull hp = pk2(hiS[i * 4 + nb]);
            ull mp = pk2(miS[i * 4 + nb]);
            float4 w1 = *(const float4*)(W1h + i * HH);
            float4 w2 = *(const float4*)(W1m + i * HH);
            fma2(a01, hp, pkf(w1.x, w1.y));
            fma2(a23, hp, pkf(w1.z, w1.w));
            fma2(a01, mp, pkf(w2.x, w2.y));
            fma2(a23, mp, pkf(w2.z, w2.w));
        }
    }
    {
        float4 bv = *(const float4*)(bn1 + cb);
        float2 u01 = up2(a01), u23 = up2(a23);
        n1S[(cb + 0) * 4 + nb] = silu_f(u01.x + bv.x);
        n1S[(cb + 1) * 4 + nb] = silu_f(u01.y + bv.y);
        n1S[(cb + 2) * 4 + nb] = silu_f(u23.x + bv.z);
        n1S[(cb + 3) * 4 + nb] = silu_f(u23.y + bv.w);
    }
    __syncthreads();

    // ---- node MLP layer 2 + residual ----
    a01 = 0ull; a23 = 0ull;
    {
        const float* W2 = Wn2 + cb;
#pragma unroll 8
        for (int i = 0; i < HH; ++i) {
            ull np = pk2(n1S[i * 4 + nb]);
            float4 w = *(const float4*)(W2 + i * HH);
            fma2(a01, np, pkf(w.x, w.y));
            fma2(a23, np, pkf(w.z, w.w));
        }
    }
    {
        float4 bv = *(const float4*)(bn2 + cb);
        float2 u01 = up2(a01), u23 = up2(a23);
        float4 res;
        res.x = u01.x + bv.x + hiS[(cb + 0) * 4 + nb];
        res.y = u01.y + bv.y + hiS[(cb + 1) * 4 + nb];
        res.z = u23.x + bv.z + hiS[(cb + 2) * 4 + nb];
        res.w = u23.y + bv.w + hiS[(cb + 3) * 4 + nb];
        *(float4*)(out + (base_bn + n0 + nb) * HH + cb) = res;
    }
}

extern "C" void kernel_launch(void* const* d_in, const int* in_sizes, int n_in,
                              void* d_out, int out_size) {
    const float* h   = (const float*)d_in[0];
    const float* x   = (const float*)d_in[1];
    const int*   ei  = (const int*)d_in[2];
    const float* We1 = (const float*)d_in[3];
    const float* be1 = (const float*)d_in[4];
    const float* We2 = (const float*)d_in[5];
    const float* be2 = (const float*)d_in[6];
    const float* Wc1 = (const float*)d_in[7];
    const float* bc1 = (const float*)d_in[8];
    const float* Wc2 = (const float*)d_in[9];
    const float* Wn1 = (const float*)d_in[10];
    const float* bn1 = (const float*)d_in[11];
    const float* Wn2 = (const float*)d_in[12];
    const float* bn2 = (const float*)d_in[13];
    float* out = (float*)d_out;

    cudaFuncSetAttribute(egnn_kernel, cudaFuncAttributeMaxDynamicSharedMemorySize,
                         SMEM_BYTES);
    dim3 grid(NB_ * NN / NPB);   // 8192 blocks
    egnn_kernel<<<grid, NTH, SMEM_BYTES>>>(h, x, ei, We1, be1, We2, be2,
                                           Wc1, bc1, Wc2, Wn1, bn1, Wn2, bn2, out);
}

// round 5
// speedup vs baseline: 1.9495x; 1.1867x over previous
#include <cuda_runtime.h>

// EGNN layer, fused per-node kernel, round 5.
// Round 3 structure, but smem shrunk (PADK 20->16, shuffle-based coord_w
// reduction instead of a 33KB smem scratch) so 3 blocks/SM fit:
// 12 warps/SM = 3 warps/SMSP for latency hiding.

#define HH   128
#define NB_  2
#define NN   16384
#define KK   16
#define NPB  4
#define PADK 16
#define NTH  128

typedef unsigned long long ull;

__device__ __forceinline__ ull pk2(float w) {
    ull r; asm("mov.b64 %0, {%1, %1};" : "=l"(r) : "f"(w)); return r;
}
__device__ __forceinline__ ull pkf(float a, float b) {
    ull r; asm("mov.b64 %0, {%1, %2};" : "=l"(r) : "f"(a), "f"(b)); return r;
}
__device__ __forceinline__ void fma2(ull &d, ull a, ull b) {
    asm("fma.rn.f32x2 %0, %1, %2, %0;" : "+l"(d) : "l"(a), "l"(b));
}
__device__ __forceinline__ float2 up2(ull v) {
    float2 f; asm("mov.b64 {%0, %1}, %2;" : "=f"(f.x), "=f"(f.y) : "l"(v)); return f;
}
__device__ __forceinline__ float silu_f(float v) { return v / (1.0f + __expf(-v)); }

// Shared-memory float offsets
#define OFF_HJT 0            // NPB*128*16 = 8192 floats (holds m_ijT in phase 3)
#define OFF_M1T 8192         // 8192 floats
#define OFF_HIS 16384        // 512 floats, layout [channel][nb]
#define OFF_MIS 16896        // 512 floats, layout [channel][nb]
#define OFF_N1S 17408        // 512 floats, layout [channel][nb]
#define OFF_SQD 17920        // 64
#define OFF_XD  17984        // 192  [nb][k][d]
#define OFF_XI  18176        // 16 (12 used)
#define OFF_CW  18192        // 64
#define OFF_IDX 18256        // 64 ints
#define SMEM_FLOATS 18320
#define SMEM_BYTES (SMEM_FLOATS * 4)

// rowbase: smem [128][16] for this warp's node. Wq = W + 4*lane (4 contiguous
// columns -> one LDG.128 per row). acc[kp][c] packs k-pair (2kp, 2kp+1).
__device__ __forceinline__ void gemm_n(const float* __restrict__ rowbase,
                                       const float* __restrict__ Wq,
                                       ull (&acc)[8][4]) {
    float4 wcur[4];
#pragma unroll
    for (int q = 0; q < 4; ++q) wcur[q] = *(const float4*)(Wq + q * HH);

#pragma unroll 1
    for (int ib = 0; ib < HH; ib += 4) {
        float4 wn[4];
#pragma unroll
        for (int q = 0; q < 4; ++q) wn[q] = make_float4(0.f, 0.f, 0.f, 0.f);
        if (ib + 4 < HH) {
#pragma unroll
            for (int q = 0; q < 4; ++q)
                wn[q] = *(const float4*)(Wq + (ib + 4 + q) * HH);
        }
#pragma unroll
        for (int q = 0; q < 4; ++q) {
            const float* bp = rowbase + (ib + q) * PADK;
            ulonglong2 v0 = *(const ulonglong2*)(bp);
            ulonglong2 v1 = *(const ulonglong2*)(bp + 4);
            ulonglong2 v2 = *(const ulonglong2*)(bp + 8);
            ulonglong2 v3 = *(const ulonglong2*)(bp + 12);
            float4 w = wcur[q];
            ull wp0 = pk2(w.x), wp1 = pk2(w.y), wp2 = pk2(w.z), wp3 = pk2(w.w);
            fma2(acc[0][0], v0.x, wp0); fma2(acc[0][1], v0.x, wp1);
            fma2(acc[0][2], v0.x, wp2); fma2(acc[0][3], v0.x, wp3);
            fma2(acc[1][0], v0.y, wp0); fma2(acc[1][1], v0.y, wp1);
            fma2(acc[1][2], v0.y, wp2); fma2(acc[1][3], v0.y, wp3);
            fma2(acc[2][0], v1.x, wp0); fma2(acc[2][1], v1.x, wp1);
            fma2(acc[2][2], v1.x, wp2); fma2(acc[2][3], v1.x, wp3);
            fma2(acc[3][0], v1.y, wp0); fma2(acc[3][1], v1.y, wp1);
            fma2(acc[3][2], v1.y, wp2); fma2(acc[3][3], v1.y, wp3);
            fma2(acc[4][0], v2.x, wp0); fma2(acc[4][1], v2.x, wp1);
            fma2(acc[4][2], v2.x, wp2); fma2(acc[4][3], v2.x, wp3);
            fma2(acc[5][0], v2.y, wp0); fma2(acc[5][1], v2.y, wp1);
            fma2(acc[5][2], v2.y, wp2); fma2(acc[5][3], v2.y, wp3);
            fma2(acc[6][0], v3.x, wp0); fma2(acc[6][1], v3.x, wp1);
            fma2(acc[6][2], v3.x, wp2); fma2(acc[6][3], v3.x, wp3);
            fma2(acc[7][0], v3.y, wp0); fma2(acc[7][1], v3.y, wp1);
            fma2(acc[7][2], v3.y, wp2); fma2(acc[7][3], v3.y, wp3);
        }
#pragma unroll
        for (int q = 0; q < 4; ++q) wcur[q] = wn[q];
    }
}

__global__ void __launch_bounds__(NTH, 3)
egnn_kernel(const float* __restrict__ h, const float* __restrict__ x,
            const int* __restrict__ eidx,
            const float* __restrict__ We1, const float* __restrict__ be1,
            const float* __restrict__ We2, const float* __restrict__ be2,
            const float* __restrict__ Wc1, const float* __restrict__ bc1,
            const float* __restrict__ Wc2,
            const float* __restrict__ Wn1, const float* __restrict__ bn1,
            const float* __restrict__ Wn2, const float* __restrict__ bn2,
            float* __restrict__ out) {
    extern __shared__ float sm[];
    float* hjT  = sm + OFF_HJT;
    float* m1T  = sm + OFF_M1T;
    float* hiS  = sm + OFF_HIS;
    float* miS  = sm + OFF_MIS;
    float* n1S  = sm + OFF_N1S;
    float* sqdS = sm + OFF_SQD;
    float* xdS  = sm + OFF_XD;
    float* xiS  = sm + OFF_XI;
    float* cwS  = sm + OFF_CW;
    int*   idxS = (int*)(sm + OFF_IDX);

    const int t    = threadIdx.x;
    const int nb   = t >> 5;       // warp = node
    const int lane = t & 31;
    const int cb   = lane * 4;     // 4 contiguous output columns
    const int g    = blockIdx.x;
    const int b    = g >> 12;      // 4096 groups per batch
    const int n0   = (g & 4095) * NPB;
    const long base_bn = (long)b * NN;

    // ---- stage inputs ----
    if (t < NPB * KK) idxS[t] = eidx[(base_bn + n0 + (t >> 4)) * KK + (t & 15)];
    if (t < NPB * 3)  xiS[t]  = x[(base_bn + n0 + t / 3) * 3 + (t % 3)];
    {
        float4 hv;
        hv.x = h[(base_bn + n0 + 0) * HH + t];
        hv.y = h[(base_bn + n0 + 1) * HH + t];
        hv.z = h[(base_bn + n0 + 2) * HH + t];
        hv.w = h[(base_bn + n0 + 3) * HH + t];
        *(float4*)(hiS + t * 4) = hv;
    }
    __syncthreads();

    // x_diff / sq_dist per edge (64 edges)
    if (t < NPB * KK) {
        int j  = idxS[t];
        int en = t >> 4;
        const float* xj = x + (base_bn + j) * 3;
        float dx = xiS[en * 3 + 0] - xj[0];
        float dy = xiS[en * 3 + 1] - xj[1];
        float dz = xiS[en * 3 + 2] - xj[2];
        xdS[t * 3 + 0] = dx; xdS[t * 3 + 1] = dy; xdS[t * 3 + 2] = dz;
        sqdS[t] = dx * dx + dy * dy + dz * dz;
    }
    // gather h_neigh, transposed into hjT[node][channel][k]
    for (int e = nb; e < NPB * KK; e += 4) {
        int j  = idxS[e];
        int en = e >> 4, k = e & 15;
        const float* hj = h + (base_bn + j) * HH;
#pragma unroll
        for (int r = 0; r < 4; ++r)
            hjT[(en * HH + lane + 32 * r) * PADK + k] = hj[lane + 32 * r];
    }
    __syncthreads();

    const float* rowH = hjT + nb * HH * PADK;
    const float* rowM = m1T + nb * HH * PADK;

    // ---- s_i = h_i @ We1[0:128, cols]  (k-invariant part of layer 1) ----
    ull s01 = 0ull, s23 = 0ull;
    {
        const float* Wq = We1 + cb;
#pragma unroll 8
        for (int i = 0; i < HH; ++i) {
            ull hp = pk2(hiS[i * 4 + nb]);
            float4 w = *(const float4*)(Wq + i * HH);
            fma2(s01, hp, pkf(w.x, w.y));
            fma2(s23, hp, pkf(w.z, w.w));
        }
    }

    ull acc[8][4];

    // ---- layer 1: m1 = silu(feat @ We1 + be1) ----
#pragma unroll
    for (int q = 0; q < 8; ++q)
#pragma unroll
        for (int c = 0; c < 4; ++c) acc[q][c] = 0ull;
    gemm_n(rowH, We1 + 128 * HH + cb, acc);
    {
        float4 b1v = *(const float4*)(be1 + cb);
        float4 wsq = *(const float4*)(We1 + 256 * HH + cb);
        float2 u01 = up2(s01), u23 = up2(s23);
        float sif[4] = {u01.x, u01.y, u23.x, u23.y};
        float b1a[4] = {b1v.x, b1v.y, b1v.z, b1v.w};
        float wsa[4] = {wsq.x, wsq.y, wsq.z, wsq.w};
#pragma unroll
        for (int c = 0; c < 4; ++c) {
            float outk[16];
#pragma unroll
            for (int kp = 0; kp < 8; ++kp) {
                float2 v = up2(acc[kp][c]);
                int k0 = kp * 2;
                outk[k0]     = silu_f(v.x + sif[c] + b1a[c] + sqdS[nb * 16 + k0] * wsa[c]);
                outk[k0 + 1] = silu_f(v.y + sif[c] + b1a[c] + sqdS[nb * 16 + k0 + 1] * wsa[c]);
            }
            float* dst = m1T + (nb * HH + cb + c) * PADK;
#pragma unroll
            for (int q = 0; q < 4; ++q)
                *(float4*)(dst + q * 4) =
                    make_float4(outk[q*4], outk[q*4+1], outk[q*4+2], outk[q*4+3]);
        }
    }
    __syncthreads();

    // ---- layer 2: m_ij = silu(m1 @ We2 + be2); m_i = sum_k m_ij ----
#pragma unroll
    for (int q = 0; q < 8; ++q)
#pragma unroll
        for (int c = 0; c < 4; ++c) acc[q][c] = 0ull;
    gemm_n(rowM, We2 + cb, acc);
    {
        float4 b2v = *(const float4*)(be2 + cb);
        float b2a[4] = {b2v.x, b2v.y, b2v.z, b2v.w};
#pragma unroll
        for (int c = 0; c < 4; ++c) {
            float outk[16];
            float ssum = 0.0f;
#pragma unroll
            for (int kp = 0; kp < 8; ++kp) {
                float2 v = up2(acc[kp][c]);
                int k0 = kp * 2;
                float m0  = silu_f(v.x + b2a[c]);
                float m1v = silu_f(v.y + b2a[c]);
                outk[k0] = m0; outk[k0 + 1] = m1v;
                ssum += m0 + m1v;
            }
            float* dst = hjT + (nb * HH + cb + c) * PADK;   // reuse hjT for m_ijT
#pragma unroll
            for (int q = 0; q < 4; ++q)
                *(float4*)(dst + q * 4) =
                    make_float4(outk[q*4], outk[q*4+1], outk[q*4+2], outk[q*4+3]);
            miS[(cb + c) * 4 + nb] = ssum;
        }
    }
    __syncthreads();

    // ---- layer 3: c1 = silu(m_ij @ Wc1 + bc1); coord_w = c1 @ Wc2 ----
#pragma unroll
    for (int q = 0; q < 8; ++q)
#pragma unroll
        for (int c = 0; c < 4; ++c) acc[q][c] = 0ull;
    gemm_n(rowH, Wc1 + cb, acc);
    {
        float4 b3v = *(const float4*)(bc1 + cb);
        float4 w2v = *(const float4*)(Wc2 + cb);
        float b3a[4] = {b3v.x, b3v.y, b3v.z, b3v.w};
        float w2a[4] = {w2v.x, w2v.y, w2v.z, w2v.w};
        // per-thread partial: sum over this lane's 4 channels, for each k
        float cw[16];
#pragma unroll
        for (int kp = 0; kp < 8; ++kp) {
            float s0 = 0.0f, s1 = 0.0f;
#pragma unroll
            for (int c = 0; c < 4; ++c) {
                float2 v = up2(acc[kp][c]);
                s0 += silu_f(v.x + b3a[c]) * w2a[c];
                s1 += silu_f(v.y + b3a[c]) * w2a[c];
            }
            cw[kp * 2] = s0; cw[kp * 2 + 1] = s1;
        }
        // butterfly reduce across the 32 lanes (all 128 channels)
#pragma unroll
        for (int off = 16; off; off >>= 1)
#pragma unroll
            for (int k = 0; k < 16; ++k)
                cw[k] += __shfl_xor_sync(0xffffffffu, cw[k], off);
        if (lane < 16) cwS[nb * 16 + lane] = cw[lane];
    }
    __syncthreads();

    // x_new
    if (t < NPB * 3) {
        int en = t / 3, d = t % 3;
        float ssum = 0.0f;
#pragma unroll
        for (int k = 0; k < KK; ++k)
            ssum += xdS[(en * 16 + k) * 3 + d] * cwS[en * 16 + k];
        out[(long)NB_ * NN * HH + (base_bn + n0 + en) * 3 + d] =
            xiS[t] + ssum * (1.0f / 16.0f);
    }

    // ---- node MLP layer 1: silu([h_i, m_i] @ Wn1 + bn1) ----
    ull a01 = 0ull, a23 = 0ull;
    {
        const float* W1h = Wn1 + cb;
        const float* W1m = Wn1 + 128 * HH + cb;
#pragma unroll 4
        for (int i = 0; i < HH; ++i) {
            ull hp = pk2(hiS[i * 4 + nb]);
            ull mp = pk2(miS[i * 4 + nb]);
            float4 w1 = *(const float4*)(W1h + i * HH);
            float4 w2 = *(const float4*)(W1m + i * HH);
            fma2(a01, hp, pkf(w1.x, w1.y));
            fma2(a23, hp, pkf(w1.z, w1.w));
            fma2(a01, mp, pkf(w2.x, w2.y));
            fma2(a23, mp, pkf(w2.z, w2.w));
        }
    }
    {
        float4 bv = *(const float4*)(bn1 + cb);
        float2 u01 = up2(a01), u23 = up2(a23);
        n1S[(cb + 0) * 4 + nb] = silu_f(u01.x + bv.x);
        n1S[(cb + 1) * 4 + nb] = silu_f(u01.y + bv.y);
        n1S[(cb + 2) * 4 + nb] = silu_f(u23.x + bv.z);
        n1S[(cb + 3) * 4 + nb] = silu_f(u23.y + bv.w);
    }
    __syncthreads();

    // ---- node MLP layer 2 + residual ----
    a01 = 0ull; a23 = 0ull;
    {
        const float* W2 = Wn2 + cb;
#pragma unroll 8
        for (int i = 0; i < HH; ++i) {
            ull np = pk2(n1S[i * 4 + nb]);
            float4 w = *(const float4*)(W2 + i * HH);
            fma2(a01, np, pkf(w.x, w.y));
            fma2(a23, np, pkf(w.z, w.w));
        }
    }
    {
        float4 bv = *(const float4*)(bn2 + cb);
        float2 u01 = up2(a01), u23 = up2(a23);
        float4 res;
        res.x = u01.x + bv.x + hiS[(cb + 0) * 4 + nb];
        res.y = u01.y + bv.y + hiS[(cb + 1) * 4 + nb];
        res.z = u23.x + bv.z + hiS[(cb + 2) * 4 + nb];
        res.w = u23.y + bv.w + hiS[(cb + 3) * 4 + nb];
        *(float4*)(out + (base_bn + n0 + nb) * HH + cb) = res;
    }
}

extern "C" void kernel_launch(void* const* d_in, const int* in_sizes, int n_in,
                              void* d_out, int out_size) {
    const float* h   = (const float*)d_in[0];
    const float* x   = (const float*)d_in[1];
    const int*   ei  = (const int*)d_in[2];
    const float* We1 = (const float*)d_in[3];
    const float* be1 = (const float*)d_in[4];
    const float* We2 = (const float*)d_in[5];
    const float* be2 = (const float*)d_in[6];
    const float* Wc1 = (const float*)d_in[7];
    const float* bc1 = (const float*)d_in[8];
    const float* Wc2 = (const float*)d_in[9];
    const float* Wn1 = (const float*)d_in[10];
    const float* bn1 = (const float*)d_in[11];
    const float* Wn2 = (const float*)d_in[12];
    const float* bn2 = (const float*)d_in[13];
    float* out = (float*)d_out;

    cudaFuncSetAttribute(egnn_kernel, cudaFuncAttributeMaxDynamicSharedMemorySize,
                         SMEM_BYTES);
    dim3 grid(NB_ * NN / NPB);   // 8192 blocks
    egnn_kernel<<<grid, NTH, SMEM_BYTES>>>(h, x, ei, We1, be1, We2, be2,
                                           Wc1, bc1, Wc2, Wn1, bn1, Wn2, bn2, out);
}

// round 6
// speedup vs baseline: 1.9557x; 1.0032x over previous
#include <cuda_runtime.h>

// EGNN layer, fused per-node kernel, round 6.
// Round 5 + XOR bank swizzle on the [channel][k] smem operand buffers:
//   word(ch, k) = ch*16 + (k ^ (ch & 12))
// Gather-transpose STS go 16-way -> 4-way conflict, epilogue STS.128 go
// 32-way -> ~8-way. GEMM reads are warp-broadcast (conflict-free) and just
// permute float4 blocks with s = ib & 12. Same smem size -> still 3 blocks/SM.

#define HH   128
#define NB_  2
#define NN   16384
#define KK   16
#define NPB  4
#define PADK 16
#define NTH  128

typedef unsigned long long ull;

__device__ __forceinline__ ull pk2(float w) {
    ull r; asm("mov.b64 %0, {%1, %1};" : "=l"(r) : "f"(w)); return r;
}
__device__ __forceinline__ ull pkf(float a, float b) {
    ull r; asm("mov.b64 %0, {%1, %2};" : "=l"(r) : "f"(a), "f"(b)); return r;
}
__device__ __forceinline__ void fma2(ull &d, ull a, ull b) {
    asm("fma.rn.f32x2 %0, %1, %2, %0;" : "+l"(d) : "l"(a), "l"(b));
}
__device__ __forceinline__ float2 up2(ull v) {
    float2 f; asm("mov.b64 {%0, %1}, %2;" : "=f"(f.x), "=f"(f.y) : "l"(v)); return f;
}
__device__ __forceinline__ float silu_f(float v) { return v / (1.0f + __expf(-v)); }

// Shared-memory float offsets
#define OFF_HJT 0            // NPB*128*16 = 8192 floats (holds m_ijT in phase 3)
#define OFF_M1T 8192         // 8192 floats
#define OFF_HIS 16384        // 512 floats, layout [channel][nb]
#define OFF_MIS 16896        // 512 floats, layout [nb][channel]
#define OFF_N1S 17408        // 512 floats, layout [nb][channel]
#define OFF_SQD 17920        // 64
#define OFF_XD  17984        // 192  [nb][k][d]
#define OFF_XI  18176        // 16 (12 used)
#define OFF_CW  18192        // 64
#define OFF_IDX 18256        // 64 ints
#define SMEM_FLOATS 18320
#define SMEM_BYTES (SMEM_FLOATS * 4)

// rowbase: smem [128][16] (swizzled) for this warp's node. Wq = W + 4*lane.
// acc[kp][c] packs k-pair (2kp, 2kp+1); kp order is LOGICAL k (swizzle is
// undone at load by permuting the float4 blocks with s = row & 12).
__device__ __forceinline__ void gemm_n(const float* __restrict__ rowbase,
                                       const float* __restrict__ Wq,
                                       ull (&acc)[8][4]) {
    float4 wcur[4];
#pragma unroll
    for (int q = 0; q < 4; ++q) wcur[q] = *(const float4*)(Wq + q * HH);

#pragma unroll 1
    for (int ib = 0; ib < HH; ib += 4) {
        float4 wn[4];
#pragma unroll
        for (int q = 0; q < 4; ++q) wn[q] = make_float4(0.f, 0.f, 0.f, 0.f);
        if (ib + 4 < HH) {
#pragma unroll
            for (int q = 0; q < 4; ++q)
                wn[q] = *(const float4*)(Wq + (ib + 4 + q) * HH);
        }
        const int s = ib & 12;   // same for ib..ib+3
#pragma unroll
        for (int q = 0; q < 4; ++q) {
            const float* bp = rowbase + (ib + q) * PADK;
            ulonglong2 v0 = *(const ulonglong2*)(bp + (0 ^ s));
            ulonglong2 v1 = *(const ulonglong2*)(bp + (4 ^ s));
            ulonglong2 v2 = *(const ulonglong2*)(bp + (8 ^ s));
            ulonglong2 v3 = *(const ulonglong2*)(bp + (12 ^ s));
            float4 w = wcur[q];
            ull wp0 = pk2(w.x), wp1 = pk2(w.y), wp2 = pk2(w.z), wp3 = pk2(w.w);
            fma2(acc[0][0], v0.x, wp0); fma2(acc[0][1], v0.x, wp1);
            fma2(acc[0][2], v0.x, wp2); fma2(acc[0][3], v0.x, wp3);
            fma2(acc[1][0], v0.y, wp0); fma2(acc[1][1], v0.y, wp1);
            fma2(acc[1][2], v0.y, wp2); fma2(acc[1][3], v0.y, wp3);
            fma2(acc[2][0], v1.x, wp0); fma2(acc[2][1], v1.x, wp1);
            fma2(acc[2][2], v1.x, wp2); fma2(acc[2][3], v1.x, wp3);
            fma2(acc[3][0], v1.y, wp0); fma2(acc[3][1], v1.y, wp1);
            fma2(acc[3][2], v1.y, wp2); fma2(acc[3][3], v1.y, wp3);
            fma2(acc[4][0], v2.x, wp0); fma2(acc[4][1], v2.x, wp1);
            fma2(acc[4][2], v2.x, wp2); fma2(acc[4][3], v2.x, wp3);
            fma2(acc[5][0], v2.y, wp0); fma2(acc[5][1], v2.y, wp1);
            fma2(acc[5][2], v2.y, wp2); fma2(acc[5][3], v2.y, wp3);
            fma2(acc[6][0], v3.x, wp0); fma2(acc[6][1], v3.x, wp1);
            fma2(acc[6][2], v3.x, wp2); fma2(acc[6][3], v3.x, wp3);
            fma2(acc[7][0], v3.y, wp0); fma2(acc[7][1], v3.y, wp1);
            fma2(acc[7][2], v3.y, wp2); fma2(acc[7][3], v3.y, wp3);
        }
#pragma unroll
        for (int q = 0; q < 4; ++q) wcur[q] = wn[q];
    }
}

__global__ void __launch_bounds__(NTH, 3)
egnn_kernel(const float* __restrict__ h, const float* __restrict__ x,
            const int* __restrict__ eidx,
            const float* __restrict__ We1, const float* __restrict__ be1,
            const float* __restrict__ We2, const float* __restrict__ be2,
            const float* __restrict__ Wc1, const float* __restrict__ bc1,
            const float* __restrict__ Wc2,
            const float* __restrict__ Wn1, const float* __restrict__ bn1,
            const float* __restrict__ Wn2, const float* __restrict__ bn2,
            float* __restrict__ out) {
    extern __shared__ float sm[];
    float* hjT  = sm + OFF_HJT;
    float* m1T  = sm + OFF_M1T;
    float* hiS  = sm + OFF_HIS;
    float* miS  = sm + OFF_MIS;
    float* n1S  = sm + OFF_N1S;
    float* sqdS = sm + OFF_SQD;
    float* xdS  = sm + OFF_XD;
    float* xiS  = sm + OFF_XI;
    float* cwS  = sm + OFF_CW;
    int*   idxS = (int*)(sm + OFF_IDX);

    const int t    = threadIdx.x;
    const int nb   = t >> 5;       // warp = node
    const int lane = t & 31;
    const int cb   = lane * 4;     // 4 contiguous output columns
    const int g    = blockIdx.x;
    const int b    = g >> 12;      // 4096 groups per batch
    const int n0   = (g & 4095) * NPB;
    const long base_bn = (long)b * NN;

    // ---- stage inputs ----
    if (t < NPB * KK) idxS[t] = eidx[(base_bn + n0 + (t >> 4)) * KK + (t & 15)];
    if (t < NPB * 3)  xiS[t]  = x[(base_bn + n0 + t / 3) * 3 + (t % 3)];
    {
        float4 hv;
        hv.x = h[(base_bn + n0 + 0) * HH + t];
        hv.y = h[(base_bn + n0 + 1) * HH + t];
        hv.z = h[(base_bn + n0 + 2) * HH + t];
        hv.w = h[(base_bn + n0 + 3) * HH + t];
        *(float4*)(hiS + t * 4) = hv;
    }
    __syncthreads();

    // x_diff / sq_dist per edge (64 edges)
    if (t < NPB * KK) {
        int j  = idxS[t];
        int en = t >> 4;
        const float* xj = x + (base_bn + j) * 3;
        float dx = xiS[en * 3 + 0] - xj[0];
        float dy = xiS[en * 3 + 1] - xj[1];
        float dz = xiS[en * 3 + 2] - xj[2];
        xdS[t * 3 + 0] = dx; xdS[t * 3 + 1] = dy; xdS[t * 3 + 2] = dz;
        sqdS[t] = dx * dx + dy * dy + dz * dz;
    }
    // gather h_neigh, transposed into hjT[node][channel][k] (swizzled).
    // ch & 12 == lane & 12 for ch = lane + 32r, so the swizzled k slot is
    // computed once per (lane, k).
    for (int e = nb; e < NPB * KK; e += 4) {
        int j  = idxS[e];
        int en = e >> 4, k = e & 15;
        int kx = k ^ (lane & 12);
        const float* hj = h + (base_bn + j) * HH;
#pragma unroll
        for (int r = 0; r < 4; ++r)
            hjT[(en * HH + lane + 32 * r) * PADK + kx] = hj[lane + 32 * r];
    }
    __syncthreads();

    const float* rowH = hjT + nb * HH * PADK;
    const float* rowM = m1T + nb * HH * PADK;
    const int xs = (lane & 3) * 4;   // epilogue swizzle: (4*lane+c) & 12

    // ---- s_i = h_i @ We1[0:128, cols]  (k-invariant part of layer 1) ----
    ull s01 = 0ull, s23 = 0ull;
    {
        const float* Wq = We1 + cb;
#pragma unroll 8
        for (int i = 0; i < HH; ++i) {
            ull hp = pk2(hiS[i * 4 + nb]);
            float4 w = *(const float4*)(Wq + i * HH);
            fma2(s01, hp, pkf(w.x, w.y));
            fma2(s23, hp, pkf(w.z, w.w));
        }
    }

    ull acc[8][4];

    // ---- layer 1: m1 = silu(feat @ We1 + be1) ----
#pragma unroll
    for (int q = 0; q < 8; ++q)
#pragma unroll
        for (int c = 0; c < 4; ++c) acc[q][c] = 0ull;
    gemm_n(rowH, We1 + 128 * HH + cb, acc);
    {
        float4 b1v = *(const float4*)(be1 + cb);
        float4 wsq = *(const float4*)(We1 + 256 * HH + cb);
        float2 u01 = up2(s01), u23 = up2(s23);
        float sif[4] = {u01.x, u01.y, u23.x, u23.y};
        float b1a[4] = {b1v.x, b1v.y, b1v.z, b1v.w};
        float wsa[4] = {wsq.x, wsq.y, wsq.z, wsq.w};
#pragma unroll
        for (int c = 0; c < 4; ++c) {
            float outk[16];
#pragma unroll
            for (int kp = 0; kp < 8; ++kp) {
                float2 v = up2(acc[kp][c]);
                int k0 = kp * 2;
                outk[k0]     = silu_f(v.x + sif[c] + b1a[c] + sqdS[nb * 16 + k0] * wsa[c]);
                outk[k0 + 1] = silu_f(v.y + sif[c] + b1a[c] + sqdS[nb * 16 + k0 + 1] * wsa[c]);
            }
            float* dst = m1T + (nb * HH + cb + c) * PADK;
#pragma unroll
            for (int q = 0; q < 4; ++q)
                *(float4*)(dst + (4 * q ^ xs)) =
                    make_float4(outk[q*4], outk[q*4+1], outk[q*4+2], outk[q*4+3]);
        }
    }
    __syncthreads();

    // ---- layer 2: m_ij = silu(m1 @ We2 + be2); m_i = sum_k m_ij ----
#pragma unroll
    for (int q = 0; q < 8; ++q)
#pragma unroll
        for (int c = 0; c < 4; ++c) acc[q][c] = 0ull;
    gemm_n(rowM, We2 + cb, acc);
    {
        float4 b2v = *(const float4*)(be2 + cb);
        float b2a[4] = {b2v.x, b2v.y, b2v.z, b2v.w};
        float mi4[4];
#pragma unroll
        for (int c = 0; c < 4; ++c) {
            float outk[16];
            float ssum = 0.0f;
#pragma unroll
            for (int kp = 0; kp < 8; ++kp) {
                float2 v = up2(acc[kp][c]);
                int k0 = kp * 2;
                float m0  = silu_f(v.x + b2a[c]);
                float m1v = silu_f(v.y + b2a[c]);
                outk[k0] = m0; outk[k0 + 1] = m1v;
                ssum += m0 + m1v;
            }
            mi4[c] = ssum;
            float* dst = hjT + (nb * HH + cb + c) * PADK;   // reuse hjT for m_ijT
#pragma unroll
            for (int q = 0; q < 4; ++q)
                *(float4*)(dst + (4 * q ^ xs)) =
                    make_float4(outk[q*4], outk[q*4+1], outk[q*4+2], outk[q*4+3]);
        }
        *(float4*)(miS + nb * HH + cb) = make_float4(mi4[0], mi4[1], mi4[2], mi4[3]);
    }
    __syncthreads();

    // ---- layer 3: c1 = silu(m_ij @ Wc1 + bc1); coord_w = c1 @ Wc2 ----
#pragma unroll
    for (int q = 0; q < 8; ++q)
#pragma unroll
        for (int c = 0; c < 4; ++c) acc[q][c] = 0ull;
    gemm_n(rowH, Wc1 + cb, acc);
    {
        float4 b3v = *(const float4*)(bc1 + cb);
        float4 w2v = *(const float4*)(Wc2 + cb);
        float b3a[4] = {b3v.x, b3v.y, b3v.z, b3v.w};
        float w2a[4] = {w2v.x, w2v.y, w2v.z, w2v.w};
        // per-thread partial: sum over this lane's 4 channels, for each k
        float cw[16];
#pragma unroll
        for (int kp = 0; kp < 8; ++kp) {
            float s0 = 0.0f, s1 = 0.0f;
#pragma unroll
            for (int c = 0; c < 4; ++c) {
                float2 v = up2(acc[kp][c]);
                s0 += silu_f(v.x + b3a[c]) * w2a[c];
                s1 += silu_f(v.y + b3a[c]) * w2a[c];
            }
            cw[kp * 2] = s0; cw[kp * 2 + 1] = s1;
        }
        // butterfly reduce across the 32 lanes (all 128 channels)
#pragma unroll
        for (int off = 16; off; off >>= 1)
#pragma unroll
            for (int k = 0; k < 16; ++k)
                cw[k] += __shfl_xor_sync(0xffffffffu, cw[k], off);
        if (lane < 16) cwS[nb * 16 + lane] = cw[lane];
    }
    __syncthreads();

    // x_new
    if (t < NPB * 3) {
        int en = t / 3, d = t % 3;
        float ssum = 0.0f;
#pragma unroll
        for (int k = 0; k < KK; ++k)
            ssum += xdS[(en * 16 + k) * 3 + d] * cwS[en * 16 + k];
        out[(long)NB_ * NN * HH + (base_bn + n0 + en) * 3 + d] =
            xiS[t] + ssum * (1.0f / 16.0f);
    }

    // ---- node MLP layer 1: silu([h_i, m_i] @ Wn1 + bn1) ----
    ull a01 = 0ull, a23 = 0ull;
    {
        const float* W1h = Wn1 + cb;
        const float* W1m = Wn1 + 128 * HH + cb;
#pragma unroll 4
        for (int i = 0; i < HH; ++i) {
            ull hp = pk2(hiS[i * 4 + nb]);
            ull mp = pk2(miS[nb * HH + i]);
            float4 w1 = *(const float4*)(W1h + i * HH);
            float4 w2 = *(const float4*)(W1m + i * HH);
            fma2(a01, hp, pkf(w1.x, w1.y));
            fma2(a23, hp, pkf(w1.z, w1.w));
            fma2(a01, mp, pkf(w2.x, w2.y));
            fma2(a23, mp, pkf(w2.z, w2.w));
        }
    }
    {
        float4 bv = *(const float4*)(bn1 + cb);
        float2 u01 = up2(a01), u23 = up2(a23);
        *(float4*)(n1S + nb * HH + cb) =
            make_float4(silu_f(u01.x + bv.x), silu_f(u01.y + bv.y),
                        silu_f(u23.x + bv.z), silu_f(u23.y + bv.w));
    }
    __syncthreads();

    // ---- node MLP layer 2 + residual ----
    a01 = 0ull; a23 = 0ull;
    {
        const float* W2 = Wn2 + cb;
#pragma unroll 8
        for (int i = 0; i < HH; ++i) {
            ull np = pk2(n1S[nb * HH + i]);
            float4 w = *(const float4*)(W2 + i * HH);
            fma2(a01, np, pkf(w.x, w.y));
            fma2(a23, np, pkf(w.z, w.w));
        }
    }
    {
        float4 bv = *(const float4*)(bn2 + cb);
        float2 u01 = up2(a01), u23 = up2(a23);
        float4 res;
        res.x = u01.x + bv.x + hiS[(cb + 0) * 4 + nb];
        res.y = u01.y + bv.y + hiS[(cb + 1) * 4 + nb];
        res.z = u23.x + bv.z + hiS[(cb + 2) * 4 + nb];
        res.w = u23.y + bv.w + hiS[(cb + 3) * 4 + nb];
        *(float4*)(out + (base_bn + n0 + nb) * HH + cb) = res;
    }
}

extern "C" void kernel_launch(void* const* d_in, const int* in_sizes, int n_in,
                              void* d_out, int out_size) {
    const float* h   = (const float*)d_in[0];
    const float* x   = (const float*)d_in[1];
    const int*   ei  = (const int*)d_in[2];
    const float* We1 = (const float*)d_in[3];
    const float* be1 = (const float*)d_in[4];
    const float* We2 = (const float*)d_in[5];
    const float* be2 = (const float*)d_in[6];
    const float* Wc1 = (const float*)d_in[7];
    const float* bc1 = (const float*)d_in[8];
    const float* Wc2 = (const float*)d_in[9];
    const float* Wn1 = (const float*)d_in[10];
    const float* bn1 = (const float*)d_in[11];
    const float* Wn2 = (const float*)d_in[12];
    const float* bn2 = (const float*)d_in[13];
    float* out = (float*)d_out;

    cudaFuncSetAttribute(egnn_kernel, cudaFuncAttributeMaxDynamicSharedMemorySize,
                         SMEM_BYTES);
    dim3 grid(NB_ * NN / NPB);   // 8192 blocks
    egnn_kernel<<<grid, NTH, SMEM_BYTES>>>(h, x, ei, We1, be1, We2, be2,
                                           Wc1, bc1, Wc2, Wn1, bn1, Wn2, bn2, out);
}

// round 7
// speedup vs baseline: 2.0636x; 1.0552x over previous
#include <cuda_runtime.h>

// EGNN layer, round 7: fully warp-independent node processing.
// Warp nb owns node nb end-to-end: stages h_i/x/idx, gathers its 16 edges,
// runs edge MLP layers, coord reduce, node MLP, and stores its outputs.
// No __syncthreads anywhere — only __syncwarp — so warps never align and
// barrier-induced issue bubbles vanish. 3 blocks/SM (12 warps).

#define HH   128
#define NB_  2
#define NN   16384
#define KK   16
#define NPB  4
#define PADK 16
#define NTH  128

typedef unsigned long long ull;

__device__ __forceinline__ ull pk2(float w) {
    ull r; asm("mov.b64 %0, {%1, %1};" : "=l"(r) : "f"(w)); return r;
}
__device__ __forceinline__ ull pkf(float a, float b) {
    ull r; asm("mov.b64 %0, {%1, %2};" : "=l"(r) : "f"(a), "f"(b)); return r;
}
__device__ __forceinline__ void fma2(ull &d, ull a, ull b) {
    asm("fma.rn.f32x2 %0, %1, %2, %0;" : "+l"(d) : "l"(a), "l"(b));
}
__device__ __forceinline__ float2 up2(ull v) {
    float2 f; asm("mov.b64 {%0, %1}, %2;" : "=f"(f.x), "=f"(f.y) : "l"(v)); return f;
}
__device__ __forceinline__ float silu_f(float v) { return v / (1.0f + __expf(-v)); }

// Shared-memory float offsets
#define OFF_HJT 0            // NPB*128*16 = 8192 floats (holds m_ijT in phase 3)
#define OFF_M1T 8192         // 8192 floats
#define OFF_HIS 16384        // 512 floats, layout [nb][channel]
#define OFF_MIS 16896        // 512 floats, layout [nb][channel]
#define OFF_N1S 17408        // 512 floats, layout [nb][channel]
#define OFF_SQD 17920        // 64
#define OFF_XD  17984        // 192  [nb][k][d]
#define OFF_XI  18176        // 16 ([nb][4], 3 used)
#define OFF_IDX 18192        // 64 ints
#define SMEM_FLOATS 18256
#define SMEM_BYTES (SMEM_FLOATS * 4)

// rowbase: smem [128][16] (swizzled) for this warp's node. Wq = W + 4*lane.
// acc[kp][c] packs logical k-pair (2kp, 2kp+1); swizzle undone at load by
// permuting float4 blocks with s = row & 12 (reads are warp-broadcast).
__device__ __forceinline__ void gemm_n(const float* __restrict__ rowbase,
                                       const float* __restrict__ Wq,
                                       ull (&acc)[8][4]) {
    float4 wcur[4];
#pragma unroll
    for (int q = 0; q < 4; ++q) wcur[q] = *(const float4*)(Wq + q * HH);

#pragma unroll 1
    for (int ib = 0; ib < HH; ib += 4) {
        float4 wn[4];
#pragma unroll
        for (int q = 0; q < 4; ++q) wn[q] = make_float4(0.f, 0.f, 0.f, 0.f);
        if (ib + 4 < HH) {
#pragma unroll
            for (int q = 0; q < 4; ++q)
                wn[q] = *(const float4*)(Wq + (ib + 4 + q) * HH);
        }
        const int s = ib & 12;   // same for ib..ib+3
#pragma unroll
        for (int q = 0; q < 4; ++q) {
            const float* bp = rowbase + (ib + q) * PADK;
            ulonglong2 v0 = *(const ulonglong2*)(bp + (0 ^ s));
            ulonglong2 v1 = *(const ulonglong2*)(bp + (4 ^ s));
            ulonglong2 v2 = *(const ulonglong2*)(bp + (8 ^ s));
            ulonglong2 v3 = *(const ulonglong2*)(bp + (12 ^ s));
            float4 w = wcur[q];
            ull wp0 = pk2(w.x), wp1 = pk2(w.y), wp2 = pk2(w.z), wp3 = pk2(w.w);
            fma2(acc[0][0], v0.x, wp0); fma2(acc[0][1], v0.x, wp1);
            fma2(acc[0][2], v0.x, wp2); fma2(acc[0][3], v0.x, wp3);
            fma2(acc[1][0], v0.y, wp0); fma2(acc[1][1], v0.y, wp1);
            fma2(acc[1][2], v0.y, wp2); fma2(acc[1][3], v0.y, wp3);
            fma2(acc[2][0], v1.x, wp0); fma2(acc[2][1], v1.x, wp1);
            fma2(acc[2][2], v1.x, wp2); fma2(acc[2][3], v1.x, wp3);
            fma2(acc[3][0], v1.y, wp0); fma2(acc[3][1], v1.y, wp1);
            fma2(acc[3][2], v1.y, wp2); fma2(acc[3][3], v1.y, wp3);
            fma2(acc[4][0], v2.x, wp0); fma2(acc[4][1], v2.x, wp1);
            fma2(acc[4][2], v2.x, wp2); fma2(acc[4][3], v2.x, wp3);
            fma2(acc[5][0], v2.y, wp0); fma2(acc[5][1], v2.y, wp1);
            fma2(acc[5][2], v2.y, wp2); fma2(acc[5][3], v2.y, wp3);
            fma2(acc[6][0], v3.x, wp0); fma2(acc[6][1], v3.x, wp1);
            fma2(acc[6][2], v3.x, wp2); fma2(acc[6][3], v3.x, wp3);
            fma2(acc[7][0], v3.y, wp0); fma2(acc[7][1], v3.y, wp1);
            fma2(acc[7][2], v3.y, wp2); fma2(acc[7][3], v3.y, wp3);
        }
#pragma unroll
        for (int q = 0; q < 4; ++q) wcur[q] = wn[q];
    }
}

__global__ void __launch_bounds__(NTH, 3)
egnn_kernel(const float* __restrict__ h, const float* __restrict__ x,
            const int* __restrict__ eidx,
            const float* __restrict__ We1, const float* __restrict__ be1,
            const float* __restrict__ We2, const float* __restrict__ be2,
            const float* __restrict__ Wc1, const float* __restrict__ bc1,
            const float* __restrict__ Wc2,
            const float* __restrict__ Wn1, const float* __restrict__ bn1,
            const float* __restrict__ Wn2, const float* __restrict__ bn2,
            float* __restrict__ out) {
    extern __shared__ float sm[];
    float* hjT  = sm + OFF_HJT;
    float* m1T  = sm + OFF_M1T;
    float* hiS  = sm + OFF_HIS;
    float* miS  = sm + OFF_MIS;
    float* n1S  = sm + OFF_N1S;
    float* sqdS = sm + OFF_SQD;
    float* xdS  = sm + OFF_XD;
    float* xiS  = sm + OFF_XI;
    int*   idxS = (int*)(sm + OFF_IDX);

    const int t    = threadIdx.x;
    const int nb   = t >> 5;       // warp = node, fully independent
    const int lane = t & 31;
    const int cb   = lane * 4;     // 4 contiguous output columns
    const int g    = blockIdx.x;
    const int b    = g >> 12;      // 4096 groups per batch
    const int n0   = (g & 4095) * NPB;
    const long base_bn = (long)b * NN;
    const long node    = base_bn + n0 + nb;

    // ---- stage inputs (warp-local) ----
    if (lane < KK) idxS[nb * KK + lane] = eidx[node * KK + lane];
    if (lane < 3)  xiS[nb * 4 + lane]   = x[node * 3 + lane];
    const float4 hi4 = *(const float4*)(h + node * HH + cb);
    *(float4*)(hiS + nb * HH + cb) = hi4;
    __syncwarp();

    // x_diff / sq_dist for this node's 16 edges
    if (lane < KK) {
        int j = idxS[nb * KK + lane];
        const float* xj = x + (base_bn + j) * 3;
        float dx = xiS[nb * 4 + 0] - xj[0];
        float dy = xiS[nb * 4 + 1] - xj[1];
        float dz = xiS[nb * 4 + 2] - xj[2];
        float* xd = xdS + (nb * KK + lane) * 3;
        xd[0] = dx; xd[1] = dy; xd[2] = dz;
        sqdS[nb * KK + lane] = dx * dx + dy * dy + dz * dz;
    }
    // gather this node's 16 neighbors into hjT[nb][channel][k] (swizzled)
    {
        const int kxb = lane & 12;
#pragma unroll 1
        for (int e = 0; e < KK; ++e) {
            int j  = idxS[nb * KK + e];
            int kx = e ^ kxb;
            const float* hj = h + (base_bn + j) * HH;
#pragma unroll
            for (int r = 0; r < 4; ++r)
                hjT[(nb * HH + lane + 32 * r) * PADK + kx] = hj[lane + 32 * r];
        }
    }
    __syncwarp();

    const float* rowH = hjT + nb * HH * PADK;
    const float* rowM = m1T + nb * HH * PADK;
    const int xs = (lane & 3) * 4;   // epilogue swizzle: (4*lane+c) & 12

    // ---- s_i = h_i @ We1[0:128, cols]  (k-invariant part of layer 1) ----
    ull s01 = 0ull, s23 = 0ull;
    {
        const float* Wq = We1 + cb;
#pragma unroll 8
        for (int i = 0; i < HH; ++i) {
            ull hp = pk2(hiS[nb * HH + i]);
            float4 w = *(const float4*)(Wq + i * HH);
            fma2(s01, hp, pkf(w.x, w.y));
            fma2(s23, hp, pkf(w.z, w.w));
        }
    }

    ull acc[8][4];

    // ---- layer 1: m1 = silu(feat @ We1 + be1) ----
#pragma unroll
    for (int q = 0; q < 8; ++q)
#pragma unroll
        for (int c = 0; c < 4; ++c) acc[q][c] = 0ull;
    gemm_n(rowH, We1 + 128 * HH + cb, acc);
    {
        float4 b1v = *(const float4*)(be1 + cb);
        float4 wsq = *(const float4*)(We1 + 256 * HH + cb);
        float2 u01 = up2(s01), u23 = up2(s23);
        float sif[4] = {u01.x, u01.y, u23.x, u23.y};
        float b1a[4] = {b1v.x, b1v.y, b1v.z, b1v.w};
        float wsa[4] = {wsq.x, wsq.y, wsq.z, wsq.w};
#pragma unroll
        for (int c = 0; c < 4; ++c) {
            float outk[16];
#pragma unroll
            for (int kp = 0; kp < 8; ++kp) {
                float2 v = up2(acc[kp][c]);
                int k0 = kp * 2;
                outk[k0]     = silu_f(v.x + sif[c] + b1a[c] + sqdS[nb * 16 + k0] * wsa[c]);
                outk[k0 + 1] = silu_f(v.y + sif[c] + b1a[c] + sqdS[nb * 16 + k0 + 1] * wsa[c]);
            }
            float* dst = m1T + (nb * HH + cb + c) * PADK;
#pragma unroll
            for (int q = 0; q < 4; ++q)
                *(float4*)(dst + (4 * q ^ xs)) =
                    make_float4(outk[q*4], outk[q*4+1], outk[q*4+2], outk[q*4+3]);
        }
    }
    __syncwarp();

    // ---- layer 2: m_ij = silu(m1 @ We2 + be2); m_i = sum_k m_ij ----
#pragma unroll
    for (int q = 0; q < 8; ++q)
#pragma unroll
        for (int c = 0; c < 4; ++c) acc[q][c] = 0ull;
    gemm_n(rowM, We2 + cb, acc);
    {
        float4 b2v = *(const float4*)(be2 + cb);
        float b2a[4] = {b2v.x, b2v.y, b2v.z, b2v.w};
        float mi4[4];
#pragma unroll
        for (int c = 0; c < 4; ++c) {
            float outk[16];
            float ssum = 0.0f;
#pragma unroll
            for (int kp = 0; kp < 8; ++kp) {
                float2 v = up2(acc[kp][c]);
                int k0 = kp * 2;
                float m0  = silu_f(v.x + b2a[c]);
                float m1v = silu_f(v.y + b2a[c]);
                outk[k0] = m0; outk[k0 + 1] = m1v;
                ssum += m0 + m1v;
            }
            mi4[c] = ssum;
            float* dst = hjT + (nb * HH + cb + c) * PADK;   // reuse hjT for m_ijT
#pragma unroll
            for (int q = 0; q < 4; ++q)
                *(float4*)(dst + (4 * q ^ xs)) =
                    make_float4(outk[q*4], outk[q*4+1], outk[q*4+2], outk[q*4+3]);
        }
        *(float4*)(miS + nb * HH + cb) = make_float4(mi4[0], mi4[1], mi4[2], mi4[3]);
    }
    __syncwarp();

    // ---- layer 3: c1 = silu(m_ij @ Wc1 + bc1); coord_w = c1 @ Wc2 ----
#pragma unroll
    for (int q = 0; q < 8; ++q)
#pragma unroll
        for (int c = 0; c < 4; ++c) acc[q][c] = 0ull;
    gemm_n(rowH, Wc1 + cb, acc);
    {
        float4 b3v = *(const float4*)(bc1 + cb);
        float4 w2v = *(const float4*)(Wc2 + cb);
        float b3a[4] = {b3v.x, b3v.y, b3v.z, b3v.w};
        float w2a[4] = {w2v.x, w2v.y, w2v.z, w2v.w};
        // per-thread partial: sum over this lane's 4 channels, for each k
        float cw[16];
#pragma unroll
        for (int kp = 0; kp < 8; ++kp) {
            float s0 = 0.0f, s1 = 0.0f;
#pragma unroll
            for (int c = 0; c < 4; ++c) {
                float2 v = up2(acc[kp][c]);
                s0 += silu_f(v.x + b3a[c]) * w2a[c];
                s1 += silu_f(v.y + b3a[c]) * w2a[c];
            }
            cw[kp * 2] = s0; cw[kp * 2 + 1] = s1;
        }
        // butterfly reduce: afterwards every lane holds all 16 coord weights
#pragma unroll
        for (int off = 16; off; off >>= 1)
#pragma unroll
            for (int k = 0; k < 16; ++k)
                cw[k] += __shfl_xor_sync(0xffffffffu, cw[k], off);

        // x_new (lanes 0..2, one spatial dim each)
        if (lane < 3) {
            float ssum = 0.0f;
#pragma unroll
            for (int k = 0; k < KK; ++k)
                ssum += xdS[(nb * 16 + k) * 3 + lane] * cw[k];
            out[(long)NB_ * NN * HH + node * 3 + lane] =
                xiS[nb * 4 + lane] + ssum * (1.0f / 16.0f);
        }
    }

    // ---- node MLP layer 1: silu([h_i, m_i] @ Wn1 + bn1) ----
    ull a01 = 0ull, a23 = 0ull;
    {
        const float* W1h = Wn1 + cb;
        const float* W1m = Wn1 + 128 * HH + cb;
#pragma unroll 4
        for (int i = 0; i < HH; ++i) {
            ull hp = pk2(hiS[nb * HH + i]);
            ull mp = pk2(miS[nb * HH + i]);
            float4 w1 = *(const float4*)(W1h + i * HH);
            float4 w2 = *(const float4*)(W1m + i * HH);
            fma2(a01, hp, pkf(w1.x, w1.y));
            fma2(a23, hp, pkf(w1.z, w1.w));
            fma2(a01, mp, pkf(w2.x, w2.y));
            fma2(a23, mp, pkf(w2.z, w2.w));
        }
    }
    {
        float4 bv = *(const float4*)(bn1 + cb);
        float2 u01 = up2(a01), u23 = up2(a23);
        *(float4*)(n1S + nb * HH + cb) =
            make_float4(silu_f(u01.x + bv.x), silu_f(u01.y + bv.y),
                        silu_f(u23.x + bv.z), silu_f(u23.y + bv.w));
    }
    __syncwarp();

    // ---- node MLP layer 2 + residual ----
    a01 = 0ull; a23 = 0ull;
    {
        const float* W2 = Wn2 + cb;
#pragma unroll 8
        for (int i = 0; i < HH; ++i) {
            ull np = pk2(n1S[nb * HH + i]);
            float4 w = *(const float4*)(W2 + i * HH);
            fma2(a01, np, pkf(w.x, w.y));
            fma2(a23, np, pkf(w.z, w.w));
        }
    }
    {
        float4 bv = *(const float4*)(bn2 + cb);
        float2 u01 = up2(a01), u23 = up2(a23);
        float4 res;
        res.x = u01.x + bv.x + hi4.x;
        res.y = u01.y + bv.y + hi4.y;
        res.z = u23.x + bv.z + hi4.z;
        res.w = u23.y + bv.w + hi4.w;
        *(float4*)(out + node * HH + cb) = res;
    }
}

extern "C" void kernel_launch(void* const* d_in, const int* in_sizes, int n_in,
                              void* d_out, int out_size) {
    const float* h   = (const float*)d_in[0];
    const float* x   = (const float*)d_in[1];
    const int*   ei  = (const int*)d_in[2];
    const float* We1 = (const float*)d_in[3];
    const float* be1 = (const float*)d_in[4];
    const float* We2 = (const float*)d_in[5];
    const float* be2 = (const float*)d_in[6];
    const float* Wc1 = (const float*)d_in[7];
    const float* bc1 = (const float*)d_in[8];
    const float* Wc2 = (const float*)d_in[9];
    const float* Wn1 = (const float*)d_in[10];
    const float* bn1 = (const float*)d_in[11];
    const float* Wn2 = (const float*)d_in[12];
    const float* bn2 = (const float*)d_in[13];
    float* out = (float*)d_out;

    cudaFuncSetAttribute(egnn_kernel, cudaFuncAttributeMaxDynamicSharedMemorySize,
                         SMEM_BYTES);
    dim3 grid(NB_ * NN / NPB);   // 8192 blocks
    egnn_kernel<<<grid, NTH, SMEM_BYTES>>>(h, x, ei, We1, be1, We2, be2,
                                           Wc1, bc1, Wc2, Wn1, bn1, Wn2, bn2, out);
}